// round 5
// baseline (speedup 1.0000x reference)
#include <cuda_runtime.h>
#include <cuda_bf16.h>
#include <math.h>
#include <stdint.h>

// ---------------- problem constants ----------------
#define BSZ   8
#define SEQ   4096
#define DMODEL 512
#define DI    1024      // d_inner
#define DS    16        // d_state
#define DR    32        // dt_rank
#define DFF   2048
#define NTOK  (BSZ*SEQ) // 32768
#define NCH   32        // scan chunks
#define CS    128       // chunk size
#define LN_EPS 1e-5f

// ---------------- scratch (device globals) ----------------
__device__ float g_xz [(size_t)NTOK*2*DI];
__device__ float g_xc [(size_t)NTOK*DI];
__device__ float g_dbc[(size_t)NTOK*64];
__device__ float g_dt [(size_t)NTOK*DI];
__device__ float g_mf [(size_t)NTOK*DMODEL];
__device__ float g_mb [(size_t)NTOK*DMODEL];
__device__ float g_h  [(size_t)NTOK*DMODEL];
__device__ float g_ff2[(size_t)NTOK*DMODEL];
__device__ float g_hend[(size_t)BSZ*NCH*DS*DI];
__device__ float g_P   [(size_t)BSZ*NCH*DS*DI];
__device__ float g_hin [(size_t)BSZ*NCH*DS*DI];
// bf16 hi/lo split operands
__device__ __nv_bfloat16 g_xh [(size_t)NTOK*DMODEL], g_xl [(size_t)NTOK*DMODEL];
__device__ __nv_bfloat16 g_xch[(size_t)NTOK*DI],     g_xcl[(size_t)NTOK*DI];
__device__ __nv_bfloat16 g_dbh[(size_t)NTOK*64],     g_dbl[(size_t)NTOK*64];
__device__ __nv_bfloat16 g_ygh[(size_t)NTOK*DI],     g_ygl[(size_t)NTOK*DI];
__device__ __nv_bfloat16 g_hh [(size_t)NTOK*DMODEL], g_hl [(size_t)NTOK*DMODEL];
__device__ __nv_bfloat16 g_f1h[(size_t)NTOK*DFF],    g_f1l[(size_t)NTOK*DFF];
__device__ __nv_bfloat16 g_wh [(size_t)2048*512],    g_wl [(size_t)2048*512];   // weight scratch
__device__ __nv_bfloat16 g_dwh[(size_t)DI*64],       g_dwl[(size_t)DI*64];

// ---------------- math helpers ----------------
__device__ __forceinline__ float sigmoidf_(float x){ return 1.f/(1.f+__expf(-x)); }
__device__ __forceinline__ float geluf(float x){
    float x3 = x*x*x;
    return 0.5f*x*(1.f + tanhf(0.7978845608028654f*(x + 0.044715f*x3)));
}
__device__ __forceinline__ float softplusf(float x){
    return fmaxf(x,0.f) + log1pf(__expf(-fabsf(x)));
}
__device__ __forceinline__ float warpSum(float v){
    #pragma unroll
    for(int o=16;o;o>>=1) v += __shfl_xor_sync(0xffffffffu, v, o);
    return v;
}
__device__ __forceinline__ uint32_t smem_u32(const void* p){
    uint32_t a;
    asm("{ .reg .u64 t; cvta.to.shared.u64 t, %1; cvt.u32.u64 %0, t; }" : "=r"(a) : "l"(p));
    return a;
}
// fp32 -> (hi trunc bf16, lo rn bf16 residual)
__device__ __forceinline__ void split1(float v, uint16_t& h, uint16_t& l){
    uint32_t b = __float_as_uint(v);
    h = (uint16_t)(b >> 16);
    __nv_bfloat16 lb = __float2bfloat16(v - __uint_as_float(b & 0xFFFF0000u));
    l = *reinterpret_cast<uint16_t*>(&lb);
}

// ---------------- portable tensor-core / async-copy primitives ----------------
#define LDSM4(r, addr) \
    asm volatile("ldmatrix.sync.aligned.m8n8.x4.shared.b16 {%0,%1,%2,%3}, [%4];" \
        : "=r"((r)[0]), "=r"((r)[1]), "=r"((r)[2]), "=r"((r)[3]) : "r"(addr))
#define MMA16816(d, a, b0, b1) \
    asm volatile("mma.sync.aligned.m16n8k16.row.col.f32.bf16.bf16.f32 " \
        "{%0,%1,%2,%3}, {%4,%5,%6,%7}, {%8,%9}, {%0,%1,%2,%3};" \
        : "+f"((d)[0]), "+f"((d)[1]), "+f"((d)[2]), "+f"((d)[3]) \
        : "r"((a)[0]), "r"((a)[1]), "r"((a)[2]), "r"((a)[3]), "r"(b0), "r"(b1))
__device__ __forceinline__ void cpasync16(uint32_t dst, const void* src){
    asm volatile("cp.async.cg.shared.global [%0], [%1], 16;" :: "r"(dst), "l"(src));
}
#define CP_COMMIT() asm volatile("cp.async.commit_group;" ::: "memory")
template<int N> __device__ __forceinline__ void cp_wait(){
    asm volatile("cp.async.wait_group %0;" :: "n"(N) : "memory");
}
__device__ __forceinline__ uint32_t swzmask(int row){ return (uint32_t)(row & 7) << 4; }

// ============================================================================
// Tensor-core GEMM (pre-split bf16 hi/lo operands, cp.async 3-stage pipeline):
//   C[M,N] = act(A[M,K](lda) @ B[N,K]^T + bias)
// exact-ish via 3 terms: Ah*Bh + Al*Bh + Ah*Bl (fp32 accum)
// CTA tile 128 x BN, K-chunk 64. 8 warps 2x4, warp tile 64 x BN/4.
// ACT: 0=none,1=gelu,2=softplus.  OUT bit0: f32, bit1: hi/lo bf16
// ============================================================================
template<int BN, int ACT, int OUT>
__global__ void __launch_bounds__(256, 1) gemm_cp(
    const __nv_bfloat16* __restrict__ Ah, const __nv_bfloat16* __restrict__ Al, int lda,
    const __nv_bfloat16* __restrict__ Bh, const __nv_bfloat16* __restrict__ Bl,
    const float* __restrict__ bias,
    float* __restrict__ Cf, __nv_bfloat16* __restrict__ Chi, __nv_bfloat16* __restrict__ Clo,
    int ldc, int M, int N, int K)
{
    extern __shared__ char smem[];
    constexpr int NT    = BN/32;
    constexpr int STAGE = 32768 + BN*256;   // Ah16K + Al16K + Bh + Bl
    const int tid = threadIdx.x, lane = tid & 31, wid = tid >> 5;
    const int warpM = wid >> 2, warpN = wid & 3;
    const int m0 = blockIdx.y*128, n0 = blockIdx.x*BN;
    const uint32_t sb = smem_u32(smem);
    const int NC = K/64;

    // ldmatrix lane-dependent address components (SW128 swizzle)
    const int a_mrow = warpM*64 + (lane & 15);
    const uint32_t aRaw  = (uint32_t)a_mrow*128 + ((lane >> 4)*16);
    const uint32_t aMask = swzmask(a_mrow);
    const int b_nrow = warpN*(BN/4) + (lane & 7) + ((lane >> 4) & 1)*8;
    const uint32_t bRaw  = (uint32_t)b_nrow*128 + (((lane >> 3) & 1)*16);
    const uint32_t bMask = swzmask(b_nrow);

    auto issue = [&](int c){
        const uint32_t st = sb + (c % 3)*STAGE;
        #pragma unroll
        for (int i = 0; i < 4; i++){              // A: 128 rows x 8 chunks
            int idx = i*256 + tid, row = idx >> 3, cc = idx & 7;
            uint32_t off = ((uint32_t)(row*128 + cc*16)) ^ swzmask(row);
            const size_t g = (size_t)(m0+row)*lda + c*64 + cc*8;
            cpasync16(st + off,         Ah + g);
            cpasync16(st + 16384 + off, Al + g);
        }
        #pragma unroll
        for (int i = 0; i < BN/32; i++){          // B: BN rows x 8 chunks
            int idx = i*256 + tid, row = idx >> 3, cc = idx & 7;
            uint32_t off = ((uint32_t)(row*128 + cc*16)) ^ swzmask(row);
            const size_t g = (size_t)(n0+row)*K + c*64 + cc*8;
            cpasync16(st + 32768 + off,          Bh + g);
            cpasync16(st + 32768 + BN*128 + off, Bl + g);
        }
        CP_COMMIT();
    };

    float acc[4][NT][4];
    #pragma unroll
    for (int mt=0; mt<4; mt++)
        #pragma unroll
        for (int nt=0; nt<NT; nt++)
            #pragma unroll
            for (int q=0; q<4; q++) acc[mt][nt][q] = 0.f;

    issue(0);
    if (NC > 1) issue(1);

    for (int c = 0; c < NC; c++){
        if (NC-1-c >= 1) cp_wait<1>(); else cp_wait<0>();
        __syncthreads();
        if (c+2 < NC) issue(c+2);

        const uint32_t stg = sb + (c % 3)*STAGE;
        #pragma unroll
        for (int ks = 0; ks < 4; ks++){
            uint32_t ah[4][4], al[4][4];
            #pragma unroll
            for (int mt = 0; mt < 4; mt++){
                uint32_t off = (aRaw + mt*2048 + ks*32) ^ aMask;
                LDSM4(ah[mt], stg + off);
                LDSM4(al[mt], stg + 16384 + off);
            }
            uint32_t bh[NT][2], bl[NT][2];
            #pragma unroll
            for (int p = 0; p < NT/2; p++){
                uint32_t off = (bRaw + p*2048 + ks*32) ^ bMask;
                uint32_t r[4];
                LDSM4(r, stg + 32768 + off);
                bh[2*p][0]=r[0]; bh[2*p][1]=r[1]; bh[2*p+1][0]=r[2]; bh[2*p+1][1]=r[3];
                LDSM4(r, stg + 32768 + BN*128 + off);
                bl[2*p][0]=r[0]; bl[2*p][1]=r[1]; bl[2*p+1][0]=r[2]; bl[2*p+1][1]=r[3];
            }
            #pragma unroll
            for (int mt = 0; mt < 4; mt++)
                #pragma unroll
                for (int nt = 0; nt < NT; nt++){
                    MMA16816(acc[mt][nt], ah[mt], bh[nt][0], bh[nt][1]);
                    MMA16816(acc[mt][nt], al[mt], bh[nt][0], bh[nt][1]);
                    MMA16816(acc[mt][nt], ah[mt], bl[nt][0], bl[nt][1]);
                }
        }
    }

    // ---- epilogue ----
    const int m_ep = m0 + warpM*64 + (lane >> 2);
    const int n_ep = n0 + warpN*(BN/4) + (lane & 3)*2;
    #pragma unroll
    for (int mt = 0; mt < 4; mt++){
        #pragma unroll
        for (int nt = 0; nt < NT; nt++){
            const int col = n_ep + nt*8;
            float b0 = bias ? bias[col]   : 0.f;
            float b1 = bias ? bias[col+1] : 0.f;
            float v0 = acc[mt][nt][0] + b0, v1 = acc[mt][nt][1] + b1;
            float v2 = acc[mt][nt][2] + b0, v3 = acc[mt][nt][3] + b1;
            if (ACT == 1){ v0=geluf(v0); v1=geluf(v1); v2=geluf(v2); v3=geluf(v3); }
            else if (ACT == 2){ v0=softplusf(v0); v1=softplusf(v1); v2=softplusf(v2); v3=softplusf(v3); }
            const int r0 = m_ep + mt*16;
            if (OUT & 1){
                *reinterpret_cast<float2*>(&Cf[(size_t)r0*ldc + col])     = make_float2(v0, v1);
                *reinterpret_cast<float2*>(&Cf[(size_t)(r0+8)*ldc + col]) = make_float2(v2, v3);
            }
            if (OUT & 2){
                uint16_t h0,l0,h1,l1,h2,l2,h3,l3;
                split1(v0,h0,l0); split1(v1,h1,l1); split1(v2,h2,l2); split1(v3,h3,l3);
                *reinterpret_cast<uint32_t*>(&Chi[(size_t)r0*ldc + col])     = (uint32_t)h0 | ((uint32_t)h1<<16);
                *reinterpret_cast<uint32_t*>(&Clo[(size_t)r0*ldc + col])     = (uint32_t)l0 | ((uint32_t)l1<<16);
                *reinterpret_cast<uint32_t*>(&Chi[(size_t)(r0+8)*ldc + col]) = (uint32_t)h2 | ((uint32_t)h3<<16);
                *reinterpret_cast<uint32_t*>(&Clo[(size_t)(r0+8)*ldc + col]) = (uint32_t)l2 | ((uint32_t)l3<<16);
            }
        }
    }
}

// ---------------- fp32 -> bf16 hi/lo split (vectorized) ----------------
__global__ void split_f32(const float4* __restrict__ src,
                          __nv_bfloat16* __restrict__ hi, __nv_bfloat16* __restrict__ lo, int n4)
{
    int idx = blockIdx.x*blockDim.x + threadIdx.x;
    if (idx >= n4) return;
    float4 v = src[idx];
    uint16_t h0,l0,h1,l1,h2,l2,h3,l3;
    split1(v.x,h0,l0); split1(v.y,h1,l1); split1(v.z,h2,l2); split1(v.w,h3,l3);
    *reinterpret_cast<uint2*>(hi + 4*(size_t)idx) =
        make_uint2((uint32_t)h0 | ((uint32_t)h1<<16), (uint32_t)h2 | ((uint32_t)h3<<16));
    *reinterpret_cast<uint2*>(lo + 4*(size_t)idx) =
        make_uint2((uint32_t)l0 | ((uint32_t)l1<<16), (uint32_t)l2 | ((uint32_t)l3<<16));
}

// ---------------- pad+split dt weights: [DI,64] = [dt_w | 0] ----------------
__global__ void pad_split_dtw(const float* __restrict__ dt_w,
                              __nv_bfloat16* __restrict__ hi, __nv_bfloat16* __restrict__ lo)
{
    int idx = blockIdx.x*blockDim.x + threadIdx.x;
    if (idx >= DI*64) return;
    int d = idx >> 6, c = idx & 63;
    float v = (c < DR) ? dt_w[d*DR + c] : 0.f;
    uint16_t h,l; split1(v,h,l);
    reinterpret_cast<uint16_t*>(hi)[idx] = h;
    reinterpret_cast<uint16_t*>(lo)[idx] = l;
}

// ---------------- depthwise conv (k=4) + bias + silu; writes f32 + hi/lo ----------------
__global__ void conv_silu_kernel(const float* __restrict__ xz,
                                 const float* __restrict__ w,
                                 const float* __restrict__ cb,
                                 float* __restrict__ xc,
                                 __nv_bfloat16* __restrict__ xch,
                                 __nv_bfloat16* __restrict__ xcl, int dir)
{
    int idx = blockIdx.x*blockDim.x + threadIdx.x;
    if (idx >= NTOK*DI) return;
    int d = idx % DI;
    int t = (idx / DI) % SEQ;
    int b =  idx / (DI*SEQ);
    const float* base = xz + ((size_t)b*SEQ)*(2*DI) + d;
    float acc = cb[d];
    #pragma unroll
    for (int j=0;j<4;j++){
        int tt = (dir==0) ? (t-3+j) : (t+3-j);
        if (tt>=0 && tt<SEQ) acc = fmaf(w[d*4+j], base[(size_t)tt*(2*DI)], acc);
    }
    float v = acc * sigmoidf_(acc);
    xc[idx] = v;
    uint16_t h,l; split1(v,h,l);
    reinterpret_cast<uint16_t*>(xch)[idx] = h;
    reinterpret_cast<uint16_t*>(xcl)[idx] = l;
}

// ---------------- chunked selective scan ----------------
__global__ void scan_pass1(const float* __restrict__ dt,
                           const float* __restrict__ xc,
                           const float* __restrict__ dbc,
                           const float* __restrict__ A_log,
                           float* __restrict__ hend, float* __restrict__ Pout,
                           int dir)
{
    const int d = blockIdx.x*blockDim.x + threadIdx.x;
    const int c = blockIdx.y, b = blockIdx.z;
    __shared__ float sB[CS][DS];
    for (int i = threadIdx.x; i < CS*DS; i += blockDim.x) {
        int sl = i / DS, q = i % DS;
        int p  = dir ? (SEQ-1 - (c*CS+sl)) : (c*CS+sl);
        sB[sl][q] = dbc[((size_t)b*SEQ + p)*64 + DR + q];
    }
    __syncthreads();

    float A[DS];
    #pragma unroll
    for (int n=0;n<DS;n++) A[n] = -__expf(A_log[d*DS + n]);

    float h[DS], P[DS];
    #pragma unroll
    for (int n=0;n<DS;n++){ h[n]=0.f; P[n]=1.f; }

    for (int s=0;s<CS;s++){
        int p = dir ? (SEQ-1 - (c*CS+s)) : (c*CS+s);
        size_t off = ((size_t)b*SEQ + p)*DI + d;
        float dtv = dt[off];
        float xv  = xc[off];
        float dtx = dtv*xv;
        #pragma unroll
        for (int n=0;n<DS;n++){
            float dA = __expf(dtv*A[n]);
            h[n] = fmaf(dA, h[n], dtx*sB[s][n]);
            P[n] *= dA;
        }
    }
    size_t base = (((size_t)b*NCH + c)*DS)*DI + d;
    #pragma unroll
    for (int n=0;n<DS;n++){ hend[base + (size_t)n*DI] = h[n]; Pout[base + (size_t)n*DI] = P[n]; }
}

__global__ void scan_pass2(const float* __restrict__ hend,
                           const float* __restrict__ P,
                           float* __restrict__ hin)
{
    int idx = blockIdx.x*blockDim.x + threadIdx.x;
    if (idx >= BSZ*DS*DI) return;
    int d = idx % DI;
    int n = (idx / DI) % DS;
    int b =  idx / (DI*DS);
    float h = 0.f;
    for (int c=0;c<NCH;c++){
        size_t off = (((size_t)b*NCH + c)*DS + n)*DI + d;
        hin[off] = h;
        h = fmaf(P[off], h, hend[off]);
    }
}

__global__ void scan_pass3(const float* __restrict__ dt,
                           const float* __restrict__ xc,
                           const float* __restrict__ dbc,
                           const float* __restrict__ A_log,
                           const float* __restrict__ Dp,
                           const float* __restrict__ xz,
                           const float* __restrict__ hin,
                           __nv_bfloat16* __restrict__ ygh,
                           __nv_bfloat16* __restrict__ ygl,
                           int dir)
{
    const int d = blockIdx.x*blockDim.x + threadIdx.x;
    const int c = blockIdx.y, b = blockIdx.z;
    __shared__ float sB[CS][DS];
    __shared__ float sC[CS][DS];
    for (int i = threadIdx.x; i < CS*2*DS; i += blockDim.x) {
        int sl = i / (2*DS), q = i % (2*DS);
        int p  = dir ? (SEQ-1 - (c*CS+sl)) : (c*CS+sl);
        float v = dbc[((size_t)b*SEQ + p)*64 + DR + q];
        if (q < DS) sB[sl][q] = v; else sC[sl][q-DS] = v;
    }
    __syncthreads();

    float A[DS];
    #pragma unroll
    for (int n=0;n<DS;n++) A[n] = -__expf(A_log[d*DS + n]);
    float h[DS];
    {
        size_t base = (((size_t)b*NCH + c)*DS)*DI + d;
        #pragma unroll
        for (int n=0;n<DS;n++) h[n] = hin[base + (size_t)n*DI];
    }
    const float Dval = Dp[d];

    for (int s=0;s<CS;s++){
        int p = dir ? (SEQ-1 - (c*CS+s)) : (c*CS+s);
        size_t off = ((size_t)b*SEQ + p)*DI + d;
        float dtv = dt[off];
        float xv  = xc[off];
        float dtx = dtv*xv;
        float y = 0.f;
        #pragma unroll
        for (int n=0;n<DS;n++){
            float dA = __expf(dtv*A[n]);
            h[n] = fmaf(dA, h[n], dtx*sB[s][n]);
            y = fmaf(h[n], sC[s][n], y);
        }
        float zz = xz[((size_t)b*SEQ + p)*(2*DI) + DI + d];
        float v = (y + xv*Dval) * (zz * sigmoidf_(zz));
        uint16_t hh,ll; split1(v,hh,ll);
        reinterpret_cast<uint16_t*>(ygh)[off] = hh;
        reinterpret_cast<uint16_t*>(ygl)[off] = ll;
    }
}

// ---------------- h = 0.5*(LN(x+mf; f) + LN(x+mb; b));  writes f32 + hi/lo ----------------
__global__ void ln_combine_kernel(const float* __restrict__ x,
                                  const float* __restrict__ mf,
                                  const float* __restrict__ mb,
                                  const float* __restrict__ gf, const float* __restrict__ bf,
                                  const float* __restrict__ gb, const float* __restrict__ bb,
                                  float* __restrict__ hout,
                                  __nv_bfloat16* __restrict__ hhi,
                                  __nv_bfloat16* __restrict__ hlo)
{
    const int row = blockIdx.x;
    const size_t base = (size_t)row*DMODEL;
    const int t4 = threadIdx.x;
    float4 x4  = *reinterpret_cast<const float4*>(&x [base + t4*4]);
    float4 f4  = *reinterpret_cast<const float4*>(&mf[base + t4*4]);
    float4 b4  = *reinterpret_cast<const float4*>(&mb[base + t4*4]);
    float a[4] = {x4.x+f4.x, x4.y+f4.y, x4.z+f4.z, x4.w+f4.w};
    float c[4] = {x4.x+b4.x, x4.y+b4.y, x4.z+b4.z, x4.w+b4.w};
    float sa=0, sa2=0, sc=0, sc2=0;
    #pragma unroll
    for (int i=0;i<4;i++){ sa+=a[i]; sa2+=a[i]*a[i]; sc+=c[i]; sc2+=c[i]*c[i]; }

    __shared__ float red[4][4];
    float vals[4] = {sa, sa2, sc, sc2};
    int warp = threadIdx.x>>5, lane = threadIdx.x&31;
    #pragma unroll
    for (int q=0;q<4;q++){
        float w = warpSum(vals[q]);
        if (lane==0) red[q][warp] = w;
    }
    __syncthreads();
    float tot[4];
    #pragma unroll
    for (int q=0;q<4;q++) tot[q] = red[q][0]+red[q][1]+red[q][2]+red[q][3];

    float ma = tot[0]*(1.f/DMODEL);
    float va = tot[1]*(1.f/DMODEL) - ma*ma;
    float ra = rsqrtf(va + LN_EPS);
    float mc = tot[2]*(1.f/DMODEL);
    float vc = tot[3]*(1.f/DMODEL) - mc*mc;
    float rc = rsqrtf(vc + LN_EPS);

    float4 out;
    float* po = &out.x;
    uint16_t hp[4], lp[4];
    #pragma unroll
    for (int i=0;i<4;i++){
        int col = t4*4+i;
        float la = (a[i]-ma)*ra*gf[col] + bf[col];
        float lc = (c[i]-mc)*rc*gb[col] + bb[col];
        float v = 0.5f*(la + lc);
        po[i] = v;
        split1(v, hp[i], lp[i]);
    }
    *reinterpret_cast<float4*>(&hout[base + t4*4]) = out;
    *reinterpret_cast<uint2*>(&hhi[base + t4*4]) =
        make_uint2((uint32_t)hp[0] | ((uint32_t)hp[1]<<16), (uint32_t)hp[2] | ((uint32_t)hp[3]<<16));
    *reinterpret_cast<uint2*>(&hlo[base + t4*4]) =
        make_uint2((uint32_t)lp[0] | ((uint32_t)lp[1]<<16), (uint32_t)lp[2] | ((uint32_t)lp[3]<<16));
}

// ---------------- out = LN(h + ff2; ln_ff) ----------------
__global__ void ln_final_kernel(const float* __restrict__ h,
                                const float* __restrict__ ff2,
                                const float* __restrict__ g, const float* __restrict__ bta,
                                float* __restrict__ out)
{
    const int row = blockIdx.x;
    const size_t base = (size_t)row*DMODEL;
    const int t4 = threadIdx.x;
    float4 h4 = *reinterpret_cast<const float4*>(&h  [base + t4*4]);
    float4 f4 = *reinterpret_cast<const float4*>(&ff2[base + t4*4]);
    float a[4] = {h4.x+f4.x, h4.y+f4.y, h4.z+f4.z, h4.w+f4.w};
    float sa=0, sa2=0;
    #pragma unroll
    for (int i=0;i<4;i++){ sa+=a[i]; sa2+=a[i]*a[i]; }

    __shared__ float red[2][4];
    int warp = threadIdx.x>>5, lane = threadIdx.x&31;
    float w0 = warpSum(sa), w1 = warpSum(sa2);
    if (lane==0){ red[0][warp]=w0; red[1][warp]=w1; }
    __syncthreads();
    float ts  = red[0][0]+red[0][1]+red[0][2]+red[0][3];
    float ts2 = red[1][0]+red[1][1]+red[1][2]+red[1][3];
    float mu = ts*(1.f/DMODEL);
    float var = ts2*(1.f/DMODEL) - mu*mu;
    float r = rsqrtf(var + LN_EPS);

    float4 o;
    float* po = &o.x;
    #pragma unroll
    for (int i=0;i<4;i++){
        int col = t4*4+i;
        po[i] = (a[i]-mu)*r*g[col] + bta[col];
    }
    *reinterpret_cast<float4*>(&out[base + t4*4]) = o;
}

// ---------------- host orchestration ----------------
extern "C" void kernel_launch(void* const* d_in, const int* in_sizes, int n_in,
                              void* d_out, int out_size)
{
    const float* x = (const float*)d_in[0];
    const float* in_w  [2] = {(const float*)d_in[1],  (const float*)d_in[10]};
    const float* conv_w[2] = {(const float*)d_in[2],  (const float*)d_in[11]};
    const float* conv_b[2] = {(const float*)d_in[3],  (const float*)d_in[12]};
    const float* xproj [2] = {(const float*)d_in[4],  (const float*)d_in[13]};
    const float* dt_w  [2] = {(const float*)d_in[5],  (const float*)d_in[14]};
    const float* dt_b  [2] = {(const float*)d_in[6],  (const float*)d_in[15]};
    const float* A_log [2] = {(const float*)d_in[7],  (const float*)d_in[16]};
    const float* Dp    [2] = {(const float*)d_in[8],  (const float*)d_in[17]};
    const float* out_w [2] = {(const float*)d_in[9],  (const float*)d_in[18]};
    const float* ln_f_g = (const float*)d_in[19];
    const float* ln_f_b = (const float*)d_in[20];
    const float* ln_b_g = (const float*)d_in[21];
    const float* ln_b_b = (const float*)d_in[22];
    const float* ln_ff_g= (const float*)d_in[23];
    const float* ln_ff_b= (const float*)d_in[24];
    const float* ffn_w1 = (const float*)d_in[25];
    const float* ffn_b1 = (const float*)d_in[26];
    const float* ffn_w2 = (const float*)d_in[27];
    const float* ffn_b2 = (const float*)d_in[28];
    float* outp = (float*)d_out;

    float *p_xz, *p_xc, *p_dbc, *p_dt, *p_mf, *p_mb, *p_h, *p_ff2;
    float *p_hend, *p_P, *p_hin;
    __nv_bfloat16 *p_xh, *p_xl, *p_xch, *p_xcl, *p_dbh, *p_dbl, *p_ygh, *p_ygl;
    __nv_bfloat16 *p_hh, *p_hl, *p_f1h, *p_f1l, *p_wh, *p_wl, *p_dwh, *p_dwl;
    cudaGetSymbolAddress((void**)&p_xz,  g_xz);
    cudaGetSymbolAddress((void**)&p_xc,  g_xc);
    cudaGetSymbolAddress((void**)&p_dbc, g_dbc);
    cudaGetSymbolAddress((void**)&p_dt,  g_dt);
    cudaGetSymbolAddress((void**)&p_mf,  g_mf);
    cudaGetSymbolAddress((void**)&p_mb,  g_mb);
    cudaGetSymbolAddress((void**)&p_h,   g_h);
    cudaGetSymbolAddress((void**)&p_ff2, g_ff2);
    cudaGetSymbolAddress((void**)&p_hend,g_hend);
    cudaGetSymbolAddress((void**)&p_P,   g_P);
    cudaGetSymbolAddress((void**)&p_hin, g_hin);
    cudaGetSymbolAddress((void**)&p_xh,  g_xh);   cudaGetSymbolAddress((void**)&p_xl,  g_xl);
    cudaGetSymbolAddress((void**)&p_xch, g_xch);  cudaGetSymbolAddress((void**)&p_xcl, g_xcl);
    cudaGetSymbolAddress((void**)&p_dbh, g_dbh);  cudaGetSymbolAddress((void**)&p_dbl, g_dbl);
    cudaGetSymbolAddress((void**)&p_ygh, g_ygh);  cudaGetSymbolAddress((void**)&p_ygl, g_ygl);
    cudaGetSymbolAddress((void**)&p_hh,  g_hh);   cudaGetSymbolAddress((void**)&p_hl,  g_hl);
    cudaGetSymbolAddress((void**)&p_f1h, g_f1h);  cudaGetSymbolAddress((void**)&p_f1l, g_f1l);
    cudaGetSymbolAddress((void**)&p_wh,  g_wh);   cudaGetSymbolAddress((void**)&p_wl,  g_wl);
    cudaGetSymbolAddress((void**)&p_dwh, g_dwh);  cudaGetSymbolAddress((void**)&p_dwl, g_dwl);

    const int SM128 = 3*(32768 + 128*256);  // 196608
    const int SM64  = 3*(32768 + 64*256);   // 147456
    cudaFuncSetAttribute(gemm_cp<128,0,1>, cudaFuncAttributeMaxDynamicSharedMemorySize, SM128);
    cudaFuncSetAttribute(gemm_cp<128,1,2>, cudaFuncAttributeMaxDynamicSharedMemorySize, SM128);
    cudaFuncSetAttribute(gemm_cp<128,2,1>, cudaFuncAttributeMaxDynamicSharedMemorySize, SM128);
    cudaFuncSetAttribute(gemm_cp<64,0,3>,  cudaFuncAttributeMaxDynamicSharedMemorySize, SM64);

    const int M = NTOK;

    // split x once
    split_f32<<<(NTOK*DMODEL/4 + 255)/256, 256>>>((const float4*)x, p_xh, p_xl, NTOK*DMODEL/4);

    for (int dir = 0; dir < 2; dir++) {
        // xz = x @ in_w^T   [M, 2048] K=512
        split_f32<<<(2*DI*DMODEL/4 + 255)/256, 256>>>((const float4*)in_w[dir], p_wh, p_wl, 2*DI*DMODEL/4);
        gemm_cp<128,0,1><<<dim3(2*DI/128, M/128), 256, SM128>>>(
            p_xh, p_xl, DMODEL, p_wh, p_wl, nullptr, p_xz, nullptr, nullptr, 2*DI, M, 2*DI, DMODEL);
        // conv + silu (writes xc f32 + hi/lo)
        conv_silu_kernel<<<(NTOK*DI)/256, 256>>>(p_xz, conv_w[dir], conv_b[dir], p_xc, p_xch, p_xcl, dir);
        // dbc = xc @ xproj^T  [M, 64] K=1024 (f32 for scan + hi/lo for dt GEMM)
        split_f32<<<(64*DI/4 + 255)/256, 256>>>((const float4*)xproj[dir], p_wh, p_wl, 64*DI/4);
        gemm_cp<64,0,3><<<dim3(1, M/128), 256, SM64>>>(
            p_xch, p_xcl, DI, p_wh, p_wl, nullptr, p_dbc, p_dbh, p_dbl, 64, M, 64, DI);
        // dt = softplus(dbc @ [dt_w|0]^T + dt_b)  [M, 1024] K=64
        pad_split_dtw<<<(DI*64)/256, 256>>>(dt_w[dir], p_dwh, p_dwl);
        gemm_cp<128,2,1><<<dim3(DI/128, M/128), 256, SM128>>>(
            p_dbh, p_dbl, 64, p_dwh, p_dwl, dt_b[dir], p_dt, nullptr, nullptr, DI, M, DI, 64);
        // chunked scan (pass3 writes yg hi/lo)
        {
            dim3 grid1(DI/256, NCH, BSZ);
            scan_pass1<<<grid1,256>>>(p_dt, p_xc, p_dbc, A_log[dir], p_hend, p_P, dir);
            scan_pass2<<<(BSZ*DS*DI)/256,256>>>(p_hend, p_P, p_hin);
            scan_pass3<<<grid1,256>>>(p_dt, p_xc, p_dbc, A_log[dir], Dp[dir], p_xz, p_hin, p_ygh, p_ygl, dir);
        }
        // mamba out = yg @ out_w^T  [M, 512] K=1024
        split_f32<<<(DMODEL*DI/4 + 255)/256, 256>>>((const float4*)out_w[dir], p_wh, p_wl, DMODEL*DI/4);
        gemm_cp<128,0,1><<<dim3(DMODEL/128, M/128), 256, SM128>>>(
            p_ygh, p_ygl, DI, p_wh, p_wl, nullptr, dir ? p_mb : p_mf, nullptr, nullptr, DMODEL, M, DMODEL, DI);
    }

    // h = 0.5*(LN(x+mf) + LN(x+mb))  (f32 + hi/lo)
    ln_combine_kernel<<<NTOK,128>>>(x, p_mf, p_mb, ln_f_g, ln_f_b, ln_b_g, ln_b_b, p_h, p_hh, p_hl);

    // ff1 = gelu(h @ w1^T + b1)  [M, 2048] K=512  (hi/lo only)
    split_f32<<<(DFF*DMODEL/4 + 255)/256, 256>>>((const float4*)ffn_w1, p_wh, p_wl, DFF*DMODEL/4);
    gemm_cp<128,1,2><<<dim3(DFF/128, M/128), 256, SM128>>>(
        p_hh, p_hl, DMODEL, p_wh, p_wl, ffn_b1, nullptr, p_f1h, p_f1l, DFF, M, DFF, DMODEL);
    // ff2 = ff1 @ w2^T + b2  [M, 512] K=2048
    split_f32<<<(DMODEL*DFF/4 + 255)/256, 256>>>((const float4*)ffn_w2, p_wh, p_wl, DMODEL*DFF/4);
    gemm_cp<128,0,1><<<dim3(DMODEL/128, M/128), 256, SM128>>>(
        p_f1h, p_f1l, DFF, p_wh, p_wl, ffn_b2, p_ff2, nullptr, nullptr, DMODEL, M, DMODEL, DFF);
    // out = LN(h + ff2)
    ln_final_kernel<<<NTOK,128>>>(p_h, p_ff2, ln_ff_g, ln_ff_b, outp);
}

// round 7
// speedup vs baseline: 1.0191x; 1.0191x over previous
#include <cuda_runtime.h>
#include <cuda_bf16.h>
#include <math.h>
#include <stdint.h>

// ---------------- problem constants ----------------
#define BSZ   8
#define SEQ   4096
#define DMODEL 512
#define DI    1024      // d_inner
#define DS    16        // d_state
#define DR    32        // dt_rank
#define DFF   2048
#define NTOK  (BSZ*SEQ) // 32768
#define NCH   32        // scan chunks
#define CS    128       // chunk size
#define LN_EPS 1e-5f

// ---------------- scratch (device globals) ----------------
__device__ float g_xz [(size_t)NTOK*2*DI];
__device__ float g_xc [(size_t)NTOK*DI];
__device__ float g_dbc[(size_t)NTOK*64];
__device__ float g_dt [(size_t)NTOK*DI];
__device__ float g_mf [(size_t)NTOK*DMODEL];
__device__ float g_mb [(size_t)NTOK*DMODEL];
__device__ float g_h  [(size_t)NTOK*DMODEL];
__device__ float g_ff2[(size_t)NTOK*DMODEL];
__device__ float g_hend[(size_t)BSZ*NCH*DS*DI];
__device__ float g_P   [(size_t)BSZ*NCH*DS*DI];
__device__ float g_hin [(size_t)BSZ*NCH*DS*DI];
// bf16 hi/lo split operands
__device__ __nv_bfloat16 g_xh [(size_t)NTOK*DMODEL], g_xl [(size_t)NTOK*DMODEL];
__device__ __nv_bfloat16 g_xch[(size_t)NTOK*DI],     g_xcl[(size_t)NTOK*DI];
__device__ __nv_bfloat16 g_dbh[(size_t)NTOK*64],     g_dbl[(size_t)NTOK*64];
__device__ __nv_bfloat16 g_ygh[(size_t)NTOK*DI],     g_ygl[(size_t)NTOK*DI];
__device__ __nv_bfloat16 g_hh [(size_t)NTOK*DMODEL], g_hl [(size_t)NTOK*DMODEL];
__device__ __nv_bfloat16 g_f1h[(size_t)NTOK*DFF],    g_f1l[(size_t)NTOK*DFF];
__device__ __nv_bfloat16 g_wh [(size_t)2048*512],    g_wl [(size_t)2048*512];   // weight scratch
__device__ __nv_bfloat16 g_dwh[(size_t)DI*64],       g_dwl[(size_t)DI*64];

// ---------------- math helpers ----------------
__device__ __forceinline__ float sigmoidf_(float x){ return 1.f/(1.f+__expf(-x)); }
__device__ __forceinline__ float geluf(float x){
    float x3 = x*x*x;
    return 0.5f*x*(1.f + tanhf(0.7978845608028654f*(x + 0.044715f*x3)));
}
__device__ __forceinline__ float softplusf(float x){
    return fmaxf(x,0.f) + log1pf(__expf(-fabsf(x)));
}
__device__ __forceinline__ float warpSum(float v){
    #pragma unroll
    for(int o=16;o;o>>=1) v += __shfl_xor_sync(0xffffffffu, v, o);
    return v;
}
__device__ __forceinline__ uint32_t smem_u32(const void* p){
    uint32_t a;
    asm("{ .reg .u64 t; cvta.to.shared.u64 t, %1; cvt.u32.u64 %0, t; }" : "=r"(a) : "l"(p));
    return a;
}
// fp32 -> (hi trunc bf16, lo rn bf16 residual)
__device__ __forceinline__ void split1(float v, uint16_t& h, uint16_t& l){
    uint32_t b = __float_as_uint(v);
    h = (uint16_t)(b >> 16);
    __nv_bfloat16 lb = __float2bfloat16(v - __uint_as_float(b & 0xFFFF0000u));
    l = *reinterpret_cast<uint16_t*>(&lb);
}

// ---------------- portable tensor-core / async-copy primitives ----------------
#define LDSM4(r, addr) \
    asm volatile("ldmatrix.sync.aligned.m8n8.x4.shared.b16 {%0,%1,%2,%3}, [%4];" \
        : "=r"((r)[0]), "=r"((r)[1]), "=r"((r)[2]), "=r"((r)[3]) : "r"(addr))
#define MMA16816(d, a, b0, b1) \
    asm volatile("mma.sync.aligned.m16n8k16.row.col.f32.bf16.bf16.f32 " \
        "{%0,%1,%2,%3}, {%4,%5,%6,%7}, {%8,%9}, {%0,%1,%2,%3};" \
        : "+f"((d)[0]), "+f"((d)[1]), "+f"((d)[2]), "+f"((d)[3]) \
        : "r"((a)[0]), "r"((a)[1]), "r"((a)[2]), "r"((a)[3]), "r"(b0), "r"(b1))
__device__ __forceinline__ void cpasync16(uint32_t dst, const void* src){
    asm volatile("cp.async.cg.shared.global [%0], [%1], 16;" :: "r"(dst), "l"(src));
}
#define CP_COMMIT() asm volatile("cp.async.commit_group;" ::: "memory")
template<int N> __device__ __forceinline__ void cp_wait(){
    asm volatile("cp.async.wait_group %0;" :: "n"(N) : "memory");
}
__device__ __forceinline__ uint32_t swzmask(int row){ return (uint32_t)(row & 7) << 4; }

// ============================================================================
// Big tensor-core GEMM: CTA tile 256x128, warps 4x2, warp tile 64x64.
//   C[M,N] = act(A[M,K](lda) @ B[N,K]^T + bias)
// pre-split bf16 hi/lo, 3 terms (AhBh+AlBh+AhBl), fp32 acc.
// 2-stage cp.async pipeline. ACT: 0=none,1=gelu,2=softplus.
// OUT bit0: f32 out, bit1: hi/lo bf16 out.
// ============================================================================
template<int ACT, int OUT>
__global__ void __launch_bounds__(256, 1) gemm256(
    const __nv_bfloat16* __restrict__ Ah, const __nv_bfloat16* __restrict__ Al, int lda,
    const __nv_bfloat16* __restrict__ Bh, const __nv_bfloat16* __restrict__ Bl,
    const float* __restrict__ bias,
    float* __restrict__ Cf, __nv_bfloat16* __restrict__ Chi, __nv_bfloat16* __restrict__ Clo,
    int ldc, int M, int N, int K)
{
    extern __shared__ char smem[];
    constexpr int STAGE = 98304;   // Ah32K + Al32K + Bh16K + Bl16K
    const int tid = threadIdx.x, lane = tid & 31, wid = tid >> 5;
    const int warpM = wid >> 1, warpN = wid & 1;      // 4 x 2
    const int m0 = blockIdx.y*256, n0 = blockIdx.x*128;
    const uint32_t sb = smem_u32(smem);
    const int NC = K/64;

    // ldmatrix lane components (SW128 swizzle)
    const int a_mrow = warpM*64 + (lane & 15);
    const uint32_t aRaw  = (uint32_t)a_mrow*128 + ((lane >> 4)*16);
    const uint32_t aMask = swzmask(a_mrow);
    const int b_nrow = warpN*64 + (lane & 7) + ((lane >> 4) & 1)*8;
    const uint32_t bRaw  = (uint32_t)b_nrow*128 + (((lane >> 3) & 1)*16);
    const uint32_t bMask = swzmask(b_nrow);

    auto issue = [&](int c){
        const uint32_t st = sb + (c & 1)*STAGE;
        #pragma unroll
        for (int i = 0; i < 8; i++){              // A: 256 rows x 8 x 16B
            int idx = i*256 + tid, row = idx >> 3, cc = idx & 7;
            uint32_t off = ((uint32_t)(row*128 + cc*16)) ^ swzmask(row);
            const size_t g = (size_t)(m0+row)*lda + c*64 + cc*8;
            cpasync16(st + off,         Ah + g);
            cpasync16(st + 32768 + off, Al + g);
        }
        #pragma unroll
        for (int i = 0; i < 4; i++){              // B: 128 rows x 8 x 16B
            int idx = i*256 + tid, row = idx >> 3, cc = idx & 7;
            uint32_t off = ((uint32_t)(row*128 + cc*16)) ^ swzmask(row);
            const size_t g = (size_t)(n0+row)*K + c*64 + cc*8;
            cpasync16(st + 65536 + off, Bh + g);
            cpasync16(st + 81920 + off, Bl + g);
        }
        CP_COMMIT();
    };

    float acc[4][8][4];
    #pragma unroll
    for (int mt=0; mt<4; mt++)
        #pragma unroll
        for (int nt=0; nt<8; nt++)
            #pragma unroll
            for (int q=0; q<4; q++) acc[mt][nt][q] = 0.f;

    issue(0);

    for (int c = 0; c < NC; c++){
        if (c+1 < NC){ issue(c+1); cp_wait<1>(); }
        else         { cp_wait<0>(); }
        __syncthreads();

        const uint32_t stg = sb + (c & 1)*STAGE;
        #pragma unroll
        for (int ks = 0; ks < 4; ks++){
            uint32_t ah[4][4], al[4][4];
            #pragma unroll
            for (int mt = 0; mt < 4; mt++){
                uint32_t off = (aRaw + mt*2048 + ks*32) ^ aMask;
                LDSM4(ah[mt], stg + off);
                LDSM4(al[mt], stg + 32768 + off);
            }
            uint32_t bh[8][2], bl[8][2];
            #pragma unroll
            for (int p = 0; p < 4; p++){
                uint32_t off = (bRaw + p*2048 + ks*32) ^ bMask;
                uint32_t r[4];
                LDSM4(r, stg + 65536 + off);
                bh[2*p][0]=r[0]; bh[2*p][1]=r[1]; bh[2*p+1][0]=r[2]; bh[2*p+1][1]=r[3];
                LDSM4(r, stg + 81920 + off);
                bl[2*p][0]=r[0]; bl[2*p][1]=r[1]; bl[2*p+1][0]=r[2]; bl[2*p+1][1]=r[3];
            }
            #pragma unroll
            for (int mt = 0; mt < 4; mt++)
                #pragma unroll
                for (int nt = 0; nt < 8; nt++){
                    MMA16816(acc[mt][nt], ah[mt], bh[nt][0], bh[nt][1]);
                    MMA16816(acc[mt][nt], al[mt], bh[nt][0], bh[nt][1]);
                    MMA16816(acc[mt][nt], ah[mt], bl[nt][0], bl[nt][1]);
                }
        }
        __syncthreads();
    }

    // ---- epilogue ----
    const int m_ep = m0 + warpM*64 + (lane >> 2);
    const int n_ep = n0 + warpN*64 + (lane & 3)*2;
    #pragma unroll
    for (int mt = 0; mt < 4; mt++){
        #pragma unroll
        for (int nt = 0; nt < 8; nt++){
            const int col = n_ep + nt*8;
            float b0 = bias ? bias[col]   : 0.f;
            float b1 = bias ? bias[col+1] : 0.f;
            float v0 = acc[mt][nt][0] + b0, v1 = acc[mt][nt][1] + b1;
            float v2 = acc[mt][nt][2] + b0, v3 = acc[mt][nt][3] + b1;
            if (ACT == 1){ v0=geluf(v0); v1=geluf(v1); v2=geluf(v2); v3=geluf(v3); }
            else if (ACT == 2){ v0=softplusf(v0); v1=softplusf(v1); v2=softplusf(v2); v3=softplusf(v3); }
            const int r0 = m_ep + mt*16;
            if (OUT & 1){
                *reinterpret_cast<float2*>(&Cf[(size_t)r0*ldc + col])     = make_float2(v0, v1);
                *reinterpret_cast<float2*>(&Cf[(size_t)(r0+8)*ldc + col]) = make_float2(v2, v3);
            }
            if (OUT & 2){
                uint16_t h0,l0,h1,l1,h2,l2,h3,l3;
                split1(v0,h0,l0); split1(v1,h1,l1); split1(v2,h2,l2); split1(v3,h3,l3);
                *reinterpret_cast<uint32_t*>(&Chi[(size_t)r0*ldc + col])     = (uint32_t)h0 | ((uint32_t)h1<<16);
                *reinterpret_cast<uint32_t*>(&Clo[(size_t)r0*ldc + col])     = (uint32_t)l0 | ((uint32_t)l1<<16);
                *reinterpret_cast<uint32_t*>(&Chi[(size_t)(r0+8)*ldc + col]) = (uint32_t)h2 | ((uint32_t)h3<<16);
                *reinterpret_cast<uint32_t*>(&Clo[(size_t)(r0+8)*ldc + col]) = (uint32_t)l2 | ((uint32_t)l3<<16);
            }
        }
    }
}

// ============================================================================
// Small GEMM for N=64 (dbc): CTA 128 x 64, 3-stage cp.async (round-4 path)
// ============================================================================
template<int ACT, int OUT>
__global__ void __launch_bounds__(256, 1) gemm_n64(
    const __nv_bfloat16* __restrict__ Ah, const __nv_bfloat16* __restrict__ Al, int lda,
    const __nv_bfloat16* __restrict__ Bh, const __nv_bfloat16* __restrict__ Bl,
    const float* __restrict__ bias,
    float* __restrict__ Cf, __nv_bfloat16* __restrict__ Chi, __nv_bfloat16* __restrict__ Clo,
    int ldc, int M, int N, int K)
{
    extern __shared__ char smem[];
    constexpr int BN = 64, NT = 2;
    constexpr int STAGE = 32768 + BN*256;
    const int tid = threadIdx.x, lane = tid & 31, wid = tid >> 5;
    const int warpM = wid >> 2, warpN = wid & 3;
    const int m0 = blockIdx.y*128, n0 = blockIdx.x*BN;
    const uint32_t sb = smem_u32(smem);
    const int NC = K/64;

    const int a_mrow = warpM*64 + (lane & 15);
    const uint32_t aRaw  = (uint32_t)a_mrow*128 + ((lane >> 4)*16);
    const uint32_t aMask = swzmask(a_mrow);
    const int b_nrow = warpN*(BN/4) + (lane & 7) + ((lane >> 4) & 1)*8;
    const uint32_t bRaw  = (uint32_t)b_nrow*128 + (((lane >> 3) & 1)*16);
    const uint32_t bMask = swzmask(b_nrow);

    auto issue = [&](int c){
        const uint32_t st = sb + (c % 3)*STAGE;
        #pragma unroll
        for (int i = 0; i < 4; i++){
            int idx = i*256 + tid, row = idx >> 3, cc = idx & 7;
            uint32_t off = ((uint32_t)(row*128 + cc*16)) ^ swzmask(row);
            const size_t g = (size_t)(m0+row)*lda + c*64 + cc*8;
            cpasync16(st + off,         Ah + g);
            cpasync16(st + 16384 + off, Al + g);
        }
        #pragma unroll
        for (int i = 0; i < BN/32; i++){
            int idx = i*256 + tid, row = idx >> 3, cc = idx & 7;
            uint32_t off = ((uint32_t)(row*128 + cc*16)) ^ swzmask(row);
            const size_t g = (size_t)(n0+row)*K + c*64 + cc*8;
            cpasync16(st + 32768 + off,          Bh + g);
            cpasync16(st + 32768 + BN*128 + off, Bl + g);
        }
        CP_COMMIT();
    };

    float acc[4][NT][4];
    #pragma unroll
    for (int mt=0; mt<4; mt++)
        #pragma unroll
        for (int nt=0; nt<NT; nt++)
            #pragma unroll
            for (int q=0; q<4; q++) acc[mt][nt][q] = 0.f;

    issue(0);
    if (NC > 1) issue(1);

    for (int c = 0; c < NC; c++){
        if (NC-1-c >= 1) cp_wait<1>(); else cp_wait<0>();
        __syncthreads();
        if (c+2 < NC) issue(c+2);

        const uint32_t stg = sb + (c % 3)*STAGE;
        #pragma unroll
        for (int ks = 0; ks < 4; ks++){
            uint32_t ah[4][4], al[4][4];
            #pragma unroll
            for (int mt = 0; mt < 4; mt++){
                uint32_t off = (aRaw + mt*2048 + ks*32) ^ aMask;
                LDSM4(ah[mt], stg + off);
                LDSM4(al[mt], stg + 16384 + off);
            }
            uint32_t bh[NT][2], bl[NT][2];
            {
                uint32_t off = (bRaw + ks*32) ^ bMask;
                uint32_t r[4];
                LDSM4(r, stg + 32768 + off);
                bh[0][0]=r[0]; bh[0][1]=r[1]; bh[1][0]=r[2]; bh[1][1]=r[3];
                LDSM4(r, stg + 32768 + BN*128 + off);
                bl[0][0]=r[0]; bl[0][1]=r[1]; bl[1][0]=r[2]; bl[1][1]=r[3];
            }
            #pragma unroll
            for (int mt = 0; mt < 4; mt++)
                #pragma unroll
                for (int nt = 0; nt < NT; nt++){
                    MMA16816(acc[mt][nt], ah[mt], bh[nt][0], bh[nt][1]);
                    MMA16816(acc[mt][nt], al[mt], bh[nt][0], bh[nt][1]);
                    MMA16816(acc[mt][nt], ah[mt], bl[nt][0], bl[nt][1]);
                }
        }
    }

    const int m_ep = m0 + warpM*64 + (lane >> 2);
    const int n_ep = n0 + warpN*(BN/4) + (lane & 3)*2;
    #pragma unroll
    for (int mt = 0; mt < 4; mt++){
        #pragma unroll
        for (int nt = 0; nt < NT; nt++){
            const int col = n_ep + nt*8;
            float b0 = bias ? bias[col]   : 0.f;
            float b1 = bias ? bias[col+1] : 0.f;
            float v0 = acc[mt][nt][0] + b0, v1 = acc[mt][nt][1] + b1;
            float v2 = acc[mt][nt][2] + b0, v3 = acc[mt][nt][3] + b1;
            if (ACT == 1){ v0=geluf(v0); v1=geluf(v1); v2=geluf(v2); v3=geluf(v3); }
            else if (ACT == 2){ v0=softplusf(v0); v1=softplusf(v1); v2=softplusf(v2); v3=softplusf(v3); }
            const int r0 = m_ep + mt*16;
            if (OUT & 1){
                *reinterpret_cast<float2*>(&Cf[(size_t)r0*ldc + col])     = make_float2(v0, v1);
                *reinterpret_cast<float2*>(&Cf[(size_t)(r0+8)*ldc + col]) = make_float2(v2, v3);
            }
            if (OUT & 2){
                uint16_t h0,l0,h1,l1,h2,l2,h3,l3;
                split1(v0,h0,l0); split1(v1,h1,l1); split1(v2,h2,l2); split1(v3,h3,l3);
                *reinterpret_cast<uint32_t*>(&Chi[(size_t)r0*ldc + col])     = (uint32_t)h0 | ((uint32_t)h1<<16);
                *reinterpret_cast<uint32_t*>(&Clo[(size_t)r0*ldc + col])     = (uint32_t)l0 | ((uint32_t)l1<<16);
                *reinterpret_cast<uint32_t*>(&Chi[(size_t)(r0+8)*ldc + col]) = (uint32_t)h2 | ((uint32_t)h3<<16);
                *reinterpret_cast<uint32_t*>(&Clo[(size_t)(r0+8)*ldc + col]) = (uint32_t)l2 | ((uint32_t)l3<<16);
            }
        }
    }
}

// ---------------- fp32 -> bf16 hi/lo split (vectorized) ----------------
__global__ void split_f32(const float4* __restrict__ src,
                          __nv_bfloat16* __restrict__ hi, __nv_bfloat16* __restrict__ lo, int n4)
{
    int idx = blockIdx.x*blockDim.x + threadIdx.x;
    if (idx >= n4) return;
    float4 v = src[idx];
    uint16_t h0,l0,h1,l1,h2,l2,h3,l3;
    split1(v.x,h0,l0); split1(v.y,h1,l1); split1(v.z,h2,l2); split1(v.w,h3,l3);
    *reinterpret_cast<uint2*>(hi + 4*(size_t)idx) =
        make_uint2((uint32_t)h0 | ((uint32_t)h1<<16), (uint32_t)h2 | ((uint32_t)h3<<16));
    *reinterpret_cast<uint2*>(lo + 4*(size_t)idx) =
        make_uint2((uint32_t)l0 | ((uint32_t)l1<<16), (uint32_t)l2 | ((uint32_t)l3<<16));
}

// ---------------- pad+split dt weights: [DI,64] = [dt_w | 0] ----------------
__global__ void pad_split_dtw(const float* __restrict__ dt_w,
                              __nv_bfloat16* __restrict__ hi, __nv_bfloat16* __restrict__ lo)
{
    int idx = blockIdx.x*blockDim.x + threadIdx.x;
    if (idx >= DI*64) return;
    int d = idx >> 6, c = idx & 63;
    float v = (c < DR) ? dt_w[d*DR + c] : 0.f;
    uint16_t h,l; split1(v,h,l);
    reinterpret_cast<uint16_t*>(hi)[idx] = h;
    reinterpret_cast<uint16_t*>(lo)[idx] = l;
}

// ---------------- depthwise conv (k=4) + bias + silu; writes f32 + hi/lo ----------------
__global__ void conv_silu_kernel(const float* __restrict__ xz,
                                 const float* __restrict__ w,
                                 const float* __restrict__ cb,
                                 float* __restrict__ xc,
                                 __nv_bfloat16* __restrict__ xch,
                                 __nv_bfloat16* __restrict__ xcl, int dir)
{
    int idx = blockIdx.x*blockDim.x + threadIdx.x;
    if (idx >= NTOK*DI) return;
    int d = idx % DI;
    int t = (idx / DI) % SEQ;
    int b =  idx / (DI*SEQ);
    const float* base = xz + ((size_t)b*SEQ)*(2*DI) + d;
    float acc = cb[d];
    #pragma unroll
    for (int j=0;j<4;j++){
        int tt = (dir==0) ? (t-3+j) : (t+3-j);
        if (tt>=0 && tt<SEQ) acc = fmaf(w[d*4+j], base[(size_t)tt*(2*DI)], acc);
    }
    float v = acc * sigmoidf_(acc);
    xc[idx] = v;
    uint16_t h,l; split1(v,h,l);
    reinterpret_cast<uint16_t*>(xch)[idx] = h;
    reinterpret_cast<uint16_t*>(xcl)[idx] = l;
}

// ---------------- chunked selective scan ----------------
__global__ void scan_pass1(const float* __restrict__ dt,
                           const float* __restrict__ xc,
                           const float* __restrict__ dbc,
                           const float* __restrict__ A_log,
                           float* __restrict__ hend, float* __restrict__ Pout,
                           int dir)
{
    const int d = blockIdx.x*blockDim.x + threadIdx.x;
    const int c = blockIdx.y, b = blockIdx.z;
    __shared__ float sB[CS][DS];
    for (int i = threadIdx.x; i < CS*DS; i += blockDim.x) {
        int sl = i / DS, q = i % DS;
        int p  = dir ? (SEQ-1 - (c*CS+sl)) : (c*CS+sl);
        sB[sl][q] = dbc[((size_t)b*SEQ + p)*64 + DR + q];
    }
    __syncthreads();

    float A[DS];
    #pragma unroll
    for (int n=0;n<DS;n++) A[n] = -__expf(A_log[d*DS + n]);

    float h[DS], P[DS];
    #pragma unroll
    for (int n=0;n<DS;n++){ h[n]=0.f; P[n]=1.f; }

    for (int s=0;s<CS;s++){
        int p = dir ? (SEQ-1 - (c*CS+s)) : (c*CS+s);
        size_t off = ((size_t)b*SEQ + p)*DI + d;
        float dtv = dt[off];
        float xv  = xc[off];
        float dtx = dtv*xv;
        #pragma unroll
        for (int n=0;n<DS;n++){
            float dA = __expf(dtv*A[n]);
            h[n] = fmaf(dA, h[n], dtx*sB[s][n]);
            P[n] *= dA;
        }
    }
    size_t base = (((size_t)b*NCH + c)*DS)*DI + d;
    #pragma unroll
    for (int n=0;n<DS;n++){ hend[base + (size_t)n*DI] = h[n]; Pout[base + (size_t)n*DI] = P[n]; }
}

__global__ void scan_pass2(const float* __restrict__ hend,
                           const float* __restrict__ P,
                           float* __restrict__ hin)
{
    int idx = blockIdx.x*blockDim.x + threadIdx.x;
    if (idx >= BSZ*DS*DI) return;
    int d = idx % DI;
    int n = (idx / DI) % DS;
    int b =  idx / (DI*DS);
    float h = 0.f;
    for (int c=0;c<NCH;c++){
        size_t off = (((size_t)b*NCH + c)*DS + n)*DI + d;
        hin[off] = h;
        h = fmaf(P[off], h, hend[off]);
    }
}

__global__ void scan_pass3(const float* __restrict__ dt,
                           const float* __restrict__ xc,
                           const float* __restrict__ dbc,
                           const float* __restrict__ A_log,
                           const float* __restrict__ Dp,
                           const float* __restrict__ xz,
                           const float* __restrict__ hin,
                           __nv_bfloat16* __restrict__ ygh,
                           __nv_bfloat16* __restrict__ ygl,
                           int dir)
{
    const int d = blockIdx.x*blockDim.x + threadIdx.x;
    const int c = blockIdx.y, b = blockIdx.z;
    __shared__ float sB[CS][DS];
    __shared__ float sC[CS][DS];
    for (int i = threadIdx.x; i < CS*2*DS; i += blockDim.x) {
        int sl = i / (2*DS), q = i % (2*DS);
        int p  = dir ? (SEQ-1 - (c*CS+sl)) : (c*CS+sl);
        float v = dbc[((size_t)b*SEQ + p)*64 + DR + q];
        if (q < DS) sB[sl][q] = v; else sC[sl][q-DS] = v;
    }
    __syncthreads();

    float A[DS];
    #pragma unroll
    for (int n=0;n<DS;n++) A[n] = -__expf(A_log[d*DS + n]);
    float h[DS];
    {
        size_t base = (((size_t)b*NCH + c)*DS)*DI + d;
        #pragma unroll
        for (int n=0;n<DS;n++) h[n] = hin[base + (size_t)n*DI];
    }
    const float Dval = Dp[d];

    for (int s=0;s<CS;s++){
        int p = dir ? (SEQ-1 - (c*CS+s)) : (c*CS+s);
        size_t off = ((size_t)b*SEQ + p)*DI + d;
        float dtv = dt[off];
        float xv  = xc[off];
        float dtx = dtv*xv;
        float y = 0.f;
        #pragma unroll
        for (int n=0;n<DS;n++){
            float dA = __expf(dtv*A[n]);
            h[n] = fmaf(dA, h[n], dtx*sB[s][n]);
            y = fmaf(h[n], sC[s][n], y);
        }
        float zz = xz[((size_t)b*SEQ + p)*(2*DI) + DI + d];
        float v = (y + xv*Dval) * (zz * sigmoidf_(zz));
        uint16_t hh,ll; split1(v,hh,ll);
        reinterpret_cast<uint16_t*>(ygh)[off] = hh;
        reinterpret_cast<uint16_t*>(ygl)[off] = ll;
    }
}

// ---------------- h = 0.5*(LN(x+mf; f) + LN(x+mb; b));  writes f32 + hi/lo ----------------
__global__ void ln_combine_kernel(const float* __restrict__ x,
                                  const float* __restrict__ mf,
                                  const float* __restrict__ mb,
                                  const float* __restrict__ gf, const float* __restrict__ bf,
                                  const float* __restrict__ gb, const float* __restrict__ bb,
                                  float* __restrict__ hout,
                                  __nv_bfloat16* __restrict__ hhi,
                                  __nv_bfloat16* __restrict__ hlo)
{
    const int row = blockIdx.x;
    const size_t base = (size_t)row*DMODEL;
    const int t4 = threadIdx.x;
    float4 x4  = *reinterpret_cast<const float4*>(&x [base + t4*4]);
    float4 f4  = *reinterpret_cast<const float4*>(&mf[base + t4*4]);
    float4 b4  = *reinterpret_cast<const float4*>(&mb[base + t4*4]);
    float a[4] = {x4.x+f4.x, x4.y+f4.y, x4.z+f4.z, x4.w+f4.w};
    float c[4] = {x4.x+b4.x, x4.y+b4.y, x4.z+b4.z, x4.w+b4.w};
    float sa=0, sa2=0, sc=0, sc2=0;
    #pragma unroll
    for (int i=0;i<4;i++){ sa+=a[i]; sa2+=a[i]*a[i]; sc+=c[i]; sc2+=c[i]*c[i]; }

    __shared__ float red[4][4];
    float vals[4] = {sa, sa2, sc, sc2};
    int warp = threadIdx.x>>5, lane = threadIdx.x&31;
    #pragma unroll
    for (int q=0;q<4;q++){
        float w = warpSum(vals[q]);
        if (lane==0) red[q][warp] = w;
    }
    __syncthreads();
    float tot[4];
    #pragma unroll
    for (int q=0;q<4;q++) tot[q] = red[q][0]+red[q][1]+red[q][2]+red[q][3];

    float ma = tot[0]*(1.f/DMODEL);
    float va = tot[1]*(1.f/DMODEL) - ma*ma;
    float ra = rsqrtf(va + LN_EPS);
    float mc = tot[2]*(1.f/DMODEL);
    float vc = tot[3]*(1.f/DMODEL) - mc*mc;
    float rc = rsqrtf(vc + LN_EPS);

    float4 out;
    float* po = &out.x;
    uint16_t hp[4], lp[4];
    #pragma unroll
    for (int i=0;i<4;i++){
        int col = t4*4+i;
        float la = (a[i]-ma)*ra*gf[col] + bf[col];
        float lc = (c[i]-mc)*rc*gb[col] + bb[col];
        float v = 0.5f*(la + lc);
        po[i] = v;
        split1(v, hp[i], lp[i]);
    }
    *reinterpret_cast<float4*>(&hout[base + t4*4]) = out;
    *reinterpret_cast<uint2*>(&hhi[base + t4*4]) =
        make_uint2((uint32_t)hp[0] | ((uint32_t)hp[1]<<16), (uint32_t)hp[2] | ((uint32_t)hp[3]<<16));
    *reinterpret_cast<uint2*>(&hlo[base + t4*4]) =
        make_uint2((uint32_t)lp[0] | ((uint32_t)lp[1]<<16), (uint32_t)lp[2] | ((uint32_t)lp[3]<<16));
}

// ---------------- out = LN(h + ff2; ln_ff) ----------------
__global__ void ln_final_kernel(const float* __restrict__ h,
                                const float* __restrict__ ff2,
                                const float* __restrict__ g, const float* __restrict__ bta,
                                float* __restrict__ out)
{
    const int row = blockIdx.x;
    const size_t base = (size_t)row*DMODEL;
    const int t4 = threadIdx.x;
    float4 h4 = *reinterpret_cast<const float4*>(&h  [base + t4*4]);
    float4 f4 = *reinterpret_cast<const float4*>(&ff2[base + t4*4]);
    float a[4] = {h4.x+f4.x, h4.y+f4.y, h4.z+f4.z, h4.w+f4.w};
    float sa=0, sa2=0;
    #pragma unroll
    for (int i=0;i<4;i++){ sa+=a[i]; sa2+=a[i]*a[i]; }

    __shared__ float red[2][4];
    int warp = threadIdx.x>>5, lane = threadIdx.x&31;
    float w0 = warpSum(sa), w1 = warpSum(sa2);
    if (lane==0){ red[0][warp]=w0; red[1][warp]=w1; }
    __syncthreads();
    float ts  = red[0][0]+red[0][1]+red[0][2]+red[0][3];
    float ts2 = red[1][0]+red[1][1]+red[1][2]+red[1][3];
    float mu = ts*(1.f/DMODEL);
    float var = ts2*(1.f/DMODEL) - mu*mu;
    float r = rsqrtf(var + LN_EPS);

    float4 o;
    float* po = &o.x;
    #pragma unroll
    for (int i=0;i<4;i++){
        int col = t4*4+i;
        po[i] = (a[i]-mu)*r*g[col] + bta[col];
    }
    *reinterpret_cast<float4*>(&out[base + t4*4]) = o;
}

// ---------------- host orchestration ----------------
extern "C" void kernel_launch(void* const* d_in, const int* in_sizes, int n_in,
                              void* d_out, int out_size)
{
    const float* x = (const float*)d_in[0];
    const float* in_w  [2] = {(const float*)d_in[1],  (const float*)d_in[10]};
    const float* conv_w[2] = {(const float*)d_in[2],  (const float*)d_in[11]};
    const float* conv_b[2] = {(const float*)d_in[3],  (const float*)d_in[12]};
    const float* xproj [2] = {(const float*)d_in[4],  (const float*)d_in[13]};
    const float* dt_w  [2] = {(const float*)d_in[5],  (const float*)d_in[14]};
    const float* dt_b  [2] = {(const float*)d_in[6],  (const float*)d_in[15]};
    const float* A_log [2] = {(const float*)d_in[7],  (const float*)d_in[16]};
    const float* Dp    [2] = {(const float*)d_in[8],  (const float*)d_in[17]};
    const float* out_w [2] = {(const float*)d_in[9],  (const float*)d_in[18]};
    const float* ln_f_g = (const float*)d_in[19];
    const float* ln_f_b = (const float*)d_in[20];
    const float* ln_b_g = (const float*)d_in[21];
    const float* ln_b_b = (const float*)d_in[22];
    const float* ln_ff_g= (const float*)d_in[23];
    const float* ln_ff_b= (const float*)d_in[24];
    const float* ffn_w1 = (const float*)d_in[25];
    const float* ffn_b1 = (const float*)d_in[26];
    const float* ffn_w2 = (const float*)d_in[27];
    const float* ffn_b2 = (const float*)d_in[28];
    float* outp = (float*)d_out;

    float *p_xz, *p_xc, *p_dbc, *p_dt, *p_mf, *p_mb, *p_h, *p_ff2;
    float *p_hend, *p_P, *p_hin;
    __nv_bfloat16 *p_xh, *p_xl, *p_xch, *p_xcl, *p_dbh, *p_dbl, *p_ygh, *p_ygl;
    __nv_bfloat16 *p_hh, *p_hl, *p_f1h, *p_f1l, *p_wh, *p_wl, *p_dwh, *p_dwl;
    cudaGetSymbolAddress((void**)&p_xz,  g_xz);
    cudaGetSymbolAddress((void**)&p_xc,  g_xc);
    cudaGetSymbolAddress((void**)&p_dbc, g_dbc);
    cudaGetSymbolAddress((void**)&p_dt,  g_dt);
    cudaGetSymbolAddress((void**)&p_mf,  g_mf);
    cudaGetSymbolAddress((void**)&p_mb,  g_mb);
    cudaGetSymbolAddress((void**)&p_h,   g_h);
    cudaGetSymbolAddress((void**)&p_ff2, g_ff2);
    cudaGetSymbolAddress((void**)&p_hend,g_hend);
    cudaGetSymbolAddress((void**)&p_P,   g_P);
    cudaGetSymbolAddress((void**)&p_hin, g_hin);
    cudaGetSymbolAddress((void**)&p_xh,  g_xh);   cudaGetSymbolAddress((void**)&p_xl,  g_xl);
    cudaGetSymbolAddress((void**)&p_xch, g_xch);  cudaGetSymbolAddress((void**)&p_xcl, g_xcl);
    cudaGetSymbolAddress((void**)&p_dbh, g_dbh);  cudaGetSymbolAddress((void**)&p_dbl, g_dbl);
    cudaGetSymbolAddress((void**)&p_ygh, g_ygh);  cudaGetSymbolAddress((void**)&p_ygl, g_ygl);
    cudaGetSymbolAddress((void**)&p_hh,  g_hh);   cudaGetSymbolAddress((void**)&p_hl,  g_hl);
    cudaGetSymbolAddress((void**)&p_f1h, g_f1h);  cudaGetSymbolAddress((void**)&p_f1l, g_f1l);
    cudaGetSymbolAddress((void**)&p_wh,  g_wh);   cudaGetSymbolAddress((void**)&p_wl,  g_wl);
    cudaGetSymbolAddress((void**)&p_dwh, g_dwh);  cudaGetSymbolAddress((void**)&p_dwl, g_dwl);

    const int SMBIG = 2*98304;              // 196608
    const int SM64  = 3*(32768 + 64*256);   // 147456
    cudaFuncSetAttribute(gemm256<0,1>, cudaFuncAttributeMaxDynamicSharedMemorySize, SMBIG);
    cudaFuncSetAttribute(gemm256<1,2>, cudaFuncAttributeMaxDynamicSharedMemorySize, SMBIG);
    cudaFuncSetAttribute(gemm256<2,1>, cudaFuncAttributeMaxDynamicSharedMemorySize, SMBIG);
    cudaFuncSetAttribute(gemm_n64<0,3>, cudaFuncAttributeMaxDynamicSharedMemorySize, SM64);

    const int M = NTOK;

    // split x once
    split_f32<<<(NTOK*DMODEL/4 + 255)/256, 256>>>((const float4*)x, p_xh, p_xl, NTOK*DMODEL/4);

    for (int dir = 0; dir < 2; dir++) {
        // xz = x @ in_w^T   [M, 2048] K=512
        split_f32<<<(2*DI*DMODEL/4 + 255)/256, 256>>>((const float4*)in_w[dir], p_wh, p_wl, 2*DI*DMODEL/4);
        gemm256<0,1><<<dim3(2*DI/128, M/256), 256, SMBIG>>>(
            p_xh, p_xl, DMODEL, p_wh, p_wl, nullptr, p_xz, nullptr, nullptr, 2*DI, M, 2*DI, DMODEL);
        // conv + silu (writes xc f32 + hi/lo)
        conv_silu_kernel<<<(NTOK*DI)/256, 256>>>(p_xz, conv_w[dir], conv_b[dir], p_xc, p_xch, p_xcl, dir);
        // dbc = xc @ xproj^T  [M, 64] K=1024 (f32 for scan + hi/lo for dt GEMM)
        split_f32<<<(64*DI/4 + 255)/256, 256>>>((const float4*)xproj[dir], p_wh, p_wl, 64*DI/4);
        gemm_n64<0,3><<<dim3(1, M/128), 256, SM64>>>(
            p_xch, p_xcl, DI, p_wh, p_wl, nullptr, p_dbc, p_dbh, p_dbl, 64, M, 64, DI);
        // dt = softplus(dbc @ [dt_w|0]^T + dt_b)  [M, 1024] K=64
        pad_split_dtw<<<(DI*64)/256, 256>>>(dt_w[dir], p_dwh, p_dwl);
        gemm256<2,1><<<dim3(DI/128, M/256), 256, SMBIG>>>(
            p_dbh, p_dbl, 64, p_dwh, p_dwl, dt_b[dir], p_dt, nullptr, nullptr, DI, M, DI, 64);
        // chunked scan (pass3 writes yg hi/lo)
        {
            dim3 grid1(DI/256, NCH, BSZ);
            scan_pass1<<<grid1,256>>>(p_dt, p_xc, p_dbc, A_log[dir], p_hend, p_P, dir);
            scan_pass2<<<(BSZ*DS*DI)/256,256>>>(p_hend, p_P, p_hin);
            scan_pass3<<<grid1,256>>>(p_dt, p_xc, p_dbc, A_log[dir], Dp[dir], p_xz, p_hin, p_ygh, p_ygl, dir);
        }
        // mamba out = yg @ out_w^T  [M, 512] K=1024
        split_f32<<<(DMODEL*DI/4 + 255)/256, 256>>>((const float4*)out_w[dir], p_wh, p_wl, DMODEL*DI/4);
        gemm256<0,1><<<dim3(DMODEL/128, M/256), 256, SMBIG>>>(
            p_ygh, p_ygl, DI, p_wh, p_wl, nullptr, dir ? p_mb : p_mf, nullptr, nullptr, DMODEL, M, DMODEL, DI);
    }

    // h = 0.5*(LN(x+mf) + LN(x+mb))  (f32 + hi/lo)
    ln_combine_kernel<<<NTOK,128>>>(x, p_mf, p_mb, ln_f_g, ln_f_b, ln_b_g, ln_b_b, p_h, p_hh, p_hl);

    // ff1 = gelu(h @ w1^T + b1)  [M, 2048] K=512  (hi/lo only)
    split_f32<<<(DFF*DMODEL/4 + 255)/256, 256>>>((const float4*)ffn_w1, p_wh, p_wl, DFF*DMODEL/4);
    gemm256<1,2><<<dim3(DFF/128, M/256), 256, SMBIG>>>(
        p_hh, p_hl, DMODEL, p_wh, p_wl, ffn_b1, nullptr, p_f1h, p_f1l, DFF, M, DFF, DMODEL);
    // ff2 = ff1 @ w2^T + b2  [M, 512] K=2048
    split_f32<<<(DMODEL*DFF/4 + 255)/256, 256>>>((const float4*)ffn_w2, p_wh, p_wl, DMODEL*DFF/4);
    gemm256<0,1><<<dim3(DMODEL/128, M/256), 256, SMBIG>>>(
        p_f1h, p_f1l, DFF, p_wh, p_wl, ffn_b2, p_ff2, nullptr, nullptr, DMODEL, M, DMODEL, DFF);
    // out = LN(h + ff2)
    ln_final_kernel<<<NTOK,128>>>(p_h, p_ff2, ln_ff_g, ln_ff_b, outp);
}

// round 11
// speedup vs baseline: 1.4351x; 1.4081x over previous
#include <cuda_runtime.h>
#include <cuda_bf16.h>
#include <math.h>
#include <stdint.h>

// ---------------- problem constants ----------------
#define BSZ   8
#define SEQ   4096
#define DMODEL 512
#define DI    1024      // d_inner
#define DS    16        // d_state
#define DR    32        // dt_rank
#define DFF   2048
#define NTOK  (BSZ*SEQ) // 32768
#define NCH   32        // scan chunks
#define CS    128       // chunk size
#define LN_EPS 1e-5f

// ---------------- scratch (device globals) ----------------
__device__ float g_xz [(size_t)NTOK*2*DI];
__device__ float g_xc [(size_t)NTOK*DI];
__device__ float g_dbc[(size_t)NTOK*64];
__device__ float g_dt [(size_t)NTOK*DI];
__device__ float g_mf [(size_t)NTOK*DMODEL];
__device__ float g_mb [(size_t)NTOK*DMODEL];
__device__ float g_h  [(size_t)NTOK*DMODEL];
__device__ float g_ff2[(size_t)NTOK*DMODEL];
__device__ float g_hend[(size_t)BSZ*NCH*DS*DI];
__device__ float g_P   [(size_t)BSZ*NCH*DS*DI];
__device__ float g_hin [(size_t)BSZ*NCH*DS*DI];
// bf16 hi/lo split operands
__device__ __nv_bfloat16 g_xh [(size_t)NTOK*DMODEL], g_xl [(size_t)NTOK*DMODEL];
__device__ __nv_bfloat16 g_xch[(size_t)NTOK*DI],     g_xcl[(size_t)NTOK*DI];
__device__ __nv_bfloat16 g_dbh[(size_t)NTOK*64],     g_dbl[(size_t)NTOK*64];
__device__ __nv_bfloat16 g_ygh[(size_t)NTOK*DI],     g_ygl[(size_t)NTOK*DI];
__device__ __nv_bfloat16 g_hh [(size_t)NTOK*DMODEL], g_hl [(size_t)NTOK*DMODEL];
__device__ __nv_bfloat16 g_f1h[(size_t)NTOK*DFF],    g_f1l[(size_t)NTOK*DFF];
__device__ __nv_bfloat16 g_wh [(size_t)2048*512],    g_wl [(size_t)2048*512];   // weight scratch
__device__ __nv_bfloat16 g_dwh[(size_t)DI*64],       g_dwl[(size_t)DI*64];

// ---------------- math helpers ----------------
__device__ __forceinline__ float sigmoidf_(float x){ return 1.f/(1.f+__expf(-x)); }
__device__ __forceinline__ float geluf(float x){
    float x3 = x*x*x;
    return 0.5f*x*(1.f + tanhf(0.7978845608028654f*(x + 0.044715f*x3)));
}
__device__ __forceinline__ float softplusf(float x){
    return fmaxf(x,0.f) + log1pf(__expf(-fabsf(x)));
}
__device__ __forceinline__ float warpSum(float v){
    #pragma unroll
    for(int o=16;o;o>>=1) v += __shfl_xor_sync(0xffffffffu, v, o);
    return v;
}
__device__ __forceinline__ uint32_t smem_u32(const void* p){
    uint32_t a;
    asm("{ .reg .u64 t; cvta.to.shared.u64 t, %1; cvt.u32.u64 %0, t; }" : "=r"(a) : "l"(p));
    return a;
}
// fp32 -> (hi trunc bf16, lo rn bf16 residual)
__device__ __forceinline__ void split1(float v, uint16_t& h, uint16_t& l){
    uint32_t b = __float_as_uint(v);
    h = (uint16_t)(b >> 16);
    __nv_bfloat16 lb = __float2bfloat16(v - __uint_as_float(b & 0xFFFF0000u));
    l = *reinterpret_cast<uint16_t*>(&lb);
}

// ---------------- portable tensor-core primitives ----------------
#define LDSM4(r, addr) \
    asm volatile("ldmatrix.sync.aligned.m8n8.x4.shared.b16 {%0,%1,%2,%3}, [%4];" \
        : "=r"((r)[0]), "=r"((r)[1]), "=r"((r)[2]), "=r"((r)[3]) : "r"(addr))
#define MMA16816(d, a, b0, b1) \
    asm volatile("mma.sync.aligned.m16n8k16.row.col.f32.bf16.bf16.f32 " \
        "{%0,%1,%2,%3}, {%4,%5,%6,%7}, {%8,%9}, {%0,%1,%2,%3};" \
        : "+f"((d)[0]), "+f"((d)[1]), "+f"((d)[2]), "+f"((d)[3]) \
        : "r"((a)[0]), "r"((a)[1]), "r"((a)[2]), "r"((a)[3]), "r"(b0), "r"(b1))
__device__ __forceinline__ uint32_t swzmask(int row){ return (uint32_t)(row & 7) << 4; }

// ============================================================================
// Tensor-core GEMM: register-staged LDG->STS (round-3 structure, fast),
// PRE-SPLIT bf16 hi/lo operands (half the LDG bytes, zero split ALU inside).
//   C[M,N] = act(A[M,K](lda) @ B[N,K]^T + bias)
// 3 terms (AhBh + AlBh + AhBl), fp32 accum. CTA 128 x BN, K-chunk 64,
// double-buffered SW128 SMEM. 8 warps 2x4, warp tile 64 x BN/4.
// ACT: 0=none,1=gelu,2=softplus.  OUT bit0: f32 out, bit1: hi/lo bf16 out.
// ============================================================================
template<int BN, int ACT, int OUT>
__global__ void __launch_bounds__(256, 1) gemm_rs(
    const __nv_bfloat16* __restrict__ Ah, const __nv_bfloat16* __restrict__ Al, int lda,
    const __nv_bfloat16* __restrict__ Bh, const __nv_bfloat16* __restrict__ Bl,
    const float* __restrict__ bias,
    float* __restrict__ Cf, __nv_bfloat16* __restrict__ Chi, __nv_bfloat16* __restrict__ Clo,
    int ldc, int M, int N, int K)
{
    extern __shared__ char smem[];
    constexpr int NT    = BN/32;            // n-tiles (of 8) per warp
    constexpr int STAGE = 32768 + 2*BN*128; // Ah16K + Al16K + Bh + Bl
    constexpr int BREG  = BN/32;            // uint4 per thread for B hi (and lo)
    const int tid = threadIdx.x, lane = tid & 31, wid = tid >> 5;
    const int warpM = wid >> 2, warpN = wid & 3;
    const int m0 = blockIdx.y*128, n0 = blockIdx.x*BN;
    const uint32_t sb = smem_u32(smem);
    const int NC = K/64;

    // ldmatrix lane-dependent address components (SW128, mask constant per lane)
    const int a_mrow = warpM*64 + (lane & 15);
    const uint32_t aRaw  = (uint32_t)a_mrow*128 + ((lane >> 4)*16);
    const uint32_t aMask = swzmask(a_mrow);
    const int b_nrow = warpN*(BN/4) + (lane & 7) + ((lane >> 4) & 1)*8;
    const uint32_t bRaw  = (uint32_t)b_nrow*128 + (((lane >> 3) & 1)*16);
    const uint32_t bMask = swzmask(b_nrow);

    float acc[4][NT][4];
    #pragma unroll
    for (int mt=0; mt<4; mt++)
        #pragma unroll
        for (int nt=0; nt<NT; nt++)
            #pragma unroll
            for (int q=0; q<4; q++) acc[mt][nt][q] = 0.f;

    uint4 rAh[4], rAl[4], rBh[BREG], rBl[BREG];

    auto loadRegs = [&](int c){
        #pragma unroll
        for (int i=0;i<4;i++){                 // A tiles: 128 rows x 128 B
            int idx = i*256 + tid; int row = idx >> 3, cc = idx & 7;
            const size_t g = (size_t)(m0+row)*lda + (size_t)c*64 + cc*8;
            rAh[i] = *reinterpret_cast<const uint4*>(Ah + g);
            rAl[i] = *reinterpret_cast<const uint4*>(Al + g);
        }
        #pragma unroll
        for (int i=0;i<BREG;i++){              // B tiles: BN rows x 128 B
            int idx = i*256 + tid; int row = idx >> 3, cc = idx & 7;
            const size_t g = (size_t)(n0+row)*K + (size_t)c*64 + cc*8;
            rBh[i] = *reinterpret_cast<const uint4*>(Bh + g);
            rBl[i] = *reinterpret_cast<const uint4*>(Bl + g);
        }
    };
    auto stsRegs = [&](int s){
        char* stg = smem + s*STAGE;
        #pragma unroll
        for (int i=0;i<4;i++){
            int idx = i*256 + tid; int row = idx >> 3, cc = idx & 7;
            uint32_t off = ((uint32_t)(row*128 + cc*16)) ^ swzmask(row);
            *reinterpret_cast<uint4*>(stg + off)         = rAh[i];
            *reinterpret_cast<uint4*>(stg + 16384 + off) = rAl[i];
        }
        #pragma unroll
        for (int i=0;i<BREG;i++){
            int idx = i*256 + tid; int row = idx >> 3, cc = idx & 7;
            uint32_t off = ((uint32_t)(row*128 + cc*16)) ^ swzmask(row);
            *reinterpret_cast<uint4*>(stg + 32768 + off)          = rBh[i];
            *reinterpret_cast<uint4*>(stg + 32768 + BN*128 + off) = rBl[i];
        }
    };

    loadRegs(0);
    stsRegs(0);
    __syncthreads();

    for (int c = 0; c < NC; c++){
        if (c+1 < NC) loadRegs(c+1);   // LDG latency overlaps the MMA block

        const uint32_t stg = sb + (c & 1)*STAGE;
        #pragma unroll
        for (int ks = 0; ks < 4; ks++){
            uint32_t ah[4][4], al[4][4];
            #pragma unroll
            for (int mt = 0; mt < 4; mt++){
                uint32_t off = (aRaw + mt*2048 + ks*32) ^ aMask;
                LDSM4(ah[mt], stg + off);
                LDSM4(al[mt], stg + 16384 + off);
            }
            uint32_t bh[NT][2], bl[NT][2];
            #pragma unroll
            for (int p = 0; p < NT/2; p++){
                uint32_t off = (bRaw + p*2048 + ks*32) ^ bMask;
                uint32_t r[4];
                LDSM4(r, stg + 32768 + off);
                bh[2*p][0]=r[0]; bh[2*p][1]=r[1]; bh[2*p+1][0]=r[2]; bh[2*p+1][1]=r[3];
                LDSM4(r, stg + 32768 + BN*128 + off);
                bl[2*p][0]=r[0]; bl[2*p][1]=r[1]; bl[2*p+1][0]=r[2]; bl[2*p+1][1]=r[3];
            }
            #pragma unroll
            for (int mt = 0; mt < 4; mt++)
                #pragma unroll
                for (int nt = 0; nt < NT; nt++){
                    MMA16816(acc[mt][nt], ah[mt], bh[nt][0], bh[nt][1]);
                    MMA16816(acc[mt][nt], al[mt], bh[nt][0], bh[nt][1]);
                    MMA16816(acc[mt][nt], ah[mt], bl[nt][0], bl[nt][1]);
                }
        }
        if (c+1 < NC) stsRegs((c+1) & 1);
        __syncthreads();
    }

    // ---- epilogue ----
    const int m_ep = m0 + warpM*64 + (lane >> 2);
    const int n_ep = n0 + warpN*(BN/4) + (lane & 3)*2;
    #pragma unroll
    for (int mt = 0; mt < 4; mt++){
        #pragma unroll
        for (int nt = 0; nt < NT; nt++){
            const int col = n_ep + nt*8;
            float b0 = bias ? bias[col]   : 0.f;
            float b1 = bias ? bias[col+1] : 0.f;
            float v0 = acc[mt][nt][0] + b0, v1 = acc[mt][nt][1] + b1;
            float v2 = acc[mt][nt][2] + b0, v3 = acc[mt][nt][3] + b1;
            if (ACT == 1){ v0=geluf(v0); v1=geluf(v1); v2=geluf(v2); v3=geluf(v3); }
            else if (ACT == 2){ v0=softplusf(v0); v1=softplusf(v1); v2=softplusf(v2); v3=softplusf(v3); }
            const int r0 = m_ep + mt*16;
            if (OUT & 1){
                *reinterpret_cast<float2*>(&Cf[(size_t)r0*ldc + col])     = make_float2(v0, v1);
                *reinterpret_cast<float2*>(&Cf[(size_t)(r0+8)*ldc + col]) = make_float2(v2, v3);
            }
            if (OUT & 2){
                uint16_t h0,l0,h1,l1,h2,l2,h3,l3;
                split1(v0,h0,l0); split1(v1,h1,l1); split1(v2,h2,l2); split1(v3,h3,l3);
                *reinterpret_cast<uint32_t*>(&Chi[(size_t)r0*ldc + col])     = (uint32_t)h0 | ((uint32_t)h1<<16);
                *reinterpret_cast<uint32_t*>(&Clo[(size_t)r0*ldc + col])     = (uint32_t)l0 | ((uint32_t)l1<<16);
                *reinterpret_cast<uint32_t*>(&Chi[(size_t)(r0+8)*ldc + col]) = (uint32_t)h2 | ((uint32_t)h3<<16);
                *reinterpret_cast<uint32_t*>(&Clo[(size_t)(r0+8)*ldc + col]) = (uint32_t)l2 | ((uint32_t)l3<<16);
            }
        }
    }
}

// ---------------- fp32 -> bf16 hi/lo split (vectorized) ----------------
__global__ void split_f32(const float4* __restrict__ src,
                          __nv_bfloat16* __restrict__ hi, __nv_bfloat16* __restrict__ lo, int n4)
{
    int idx = blockIdx.x*blockDim.x + threadIdx.x;
    if (idx >= n4) return;
    float4 v = src[idx];
    uint16_t h0,l0,h1,l1,h2,l2,h3,l3;
    split1(v.x,h0,l0); split1(v.y,h1,l1); split1(v.z,h2,l2); split1(v.w,h3,l3);
    *reinterpret_cast<uint2*>(hi + 4*(size_t)idx) =
        make_uint2((uint32_t)h0 | ((uint32_t)h1<<16), (uint32_t)h2 | ((uint32_t)h3<<16));
    *reinterpret_cast<uint2*>(lo + 4*(size_t)idx) =
        make_uint2((uint32_t)l0 | ((uint32_t)l1<<16), (uint32_t)l2 | ((uint32_t)l3<<16));
}

// ---------------- pad+split dt weights: [DI,64] = [dt_w | 0] ----------------
__global__ void pad_split_dtw(const float* __restrict__ dt_w,
                              __nv_bfloat16* __restrict__ hi, __nv_bfloat16* __restrict__ lo)
{
    int idx = blockIdx.x*blockDim.x + threadIdx.x;
    if (idx >= DI*64) return;
    int d = idx >> 6, c = idx & 63;
    float v = (c < DR) ? dt_w[d*DR + c] : 0.f;
    uint16_t h,l; split1(v,h,l);
    reinterpret_cast<uint16_t*>(hi)[idx] = h;
    reinterpret_cast<uint16_t*>(lo)[idx] = l;
}

// ---------------- depthwise conv (k=4) + bias + silu; float4 vectorized ----------------
__global__ void conv_silu_kernel(const float* __restrict__ xz,
                                 const float* __restrict__ w,
                                 const float* __restrict__ cb,
                                 float* __restrict__ xc,
                                 __nv_bfloat16* __restrict__ xch,
                                 __nv_bfloat16* __restrict__ xcl, int dir)
{
    int idx = blockIdx.x*blockDim.x + threadIdx.x;   // over NTOK*DI/4
    if (idx >= NTOK*DI/4) return;
    int d4 = idx % (DI/4);
    int t  = (idx / (DI/4)) % SEQ;
    int b  =  idx / ((DI/4)*SEQ);
    const int d = d4*4;
    const float* base = xz + ((size_t)b*SEQ)*(2*DI) + d;
    float4 wr[4];
    #pragma unroll
    for (int q=0;q<4;q++) wr[q] = *reinterpret_cast<const float4*>(w + (d+q)*4);
    float4 bias4 = *reinterpret_cast<const float4*>(cb + d);
    float acc[4] = {bias4.x, bias4.y, bias4.z, bias4.w};
    #pragma unroll
    for (int j=0;j<4;j++){
        int tt = (dir==0) ? (t-3+j) : (t+3-j);
        if (tt>=0 && tt<SEQ){
            float4 v = *reinterpret_cast<const float4*>(base + (size_t)tt*(2*DI));
            acc[0] = fmaf((&wr[0].x)[j], v.x, acc[0]);
            acc[1] = fmaf((&wr[1].x)[j], v.y, acc[1]);
            acc[2] = fmaf((&wr[2].x)[j], v.z, acc[2]);
            acc[3] = fmaf((&wr[3].x)[j], v.w, acc[3]);
        }
    }
    float4 out;
    uint16_t h[4], l[4];
    #pragma unroll
    for (int q=0;q<4;q++){
        float v = acc[q] * sigmoidf_(acc[q]);
        (&out.x)[q] = v;
        split1(v, h[q], l[q]);
    }
    size_t o = 4*(size_t)idx;
    *reinterpret_cast<float4*>(xc + o) = out;
    *reinterpret_cast<uint2*>(xch + o) =
        make_uint2((uint32_t)h[0] | ((uint32_t)h[1]<<16), (uint32_t)h[2] | ((uint32_t)h[3]<<16));
    *reinterpret_cast<uint2*>(xcl + o) =
        make_uint2((uint32_t)l[0] | ((uint32_t)l[1]<<16), (uint32_t)l[2] | ((uint32_t)l[3]<<16));
}

// ---------------- chunked selective scan ----------------
__global__ void scan_pass1(const float* __restrict__ dt,
                           const float* __restrict__ xc,
                           const float* __restrict__ dbc,
                           const float* __restrict__ A_log,
                           float* __restrict__ hend, float* __restrict__ Pout,
                           int dir)
{
    const int d = blockIdx.x*blockDim.x + threadIdx.x;
    const int c = blockIdx.y, b = blockIdx.z;
    __shared__ float sB[CS][DS];
    for (int i = threadIdx.x; i < CS*DS; i += blockDim.x) {
        int sl = i / DS, q = i % DS;
        int p  = dir ? (SEQ-1 - (c*CS+sl)) : (c*CS+sl);
        sB[sl][q] = dbc[((size_t)b*SEQ + p)*64 + DR + q];
    }
    __syncthreads();

    float A[DS];
    #pragma unroll
    for (int n=0;n<DS;n++) A[n] = -__expf(A_log[d*DS + n]);

    float h[DS], P[DS];
    #pragma unroll
    for (int n=0;n<DS;n++){ h[n]=0.f; P[n]=1.f; }

    for (int s=0;s<CS;s++){
        int p = dir ? (SEQ-1 - (c*CS+s)) : (c*CS+s);
        size_t off = ((size_t)b*SEQ + p)*DI + d;
        float dtv = dt[off];
        float xv  = xc[off];
        float dtx = dtv*xv;
        #pragma unroll
        for (int n=0;n<DS;n++){
            float dA = __expf(dtv*A[n]);
            h[n] = fmaf(dA, h[n], dtx*sB[s][n]);
            P[n] *= dA;
        }
    }
    size_t base = (((size_t)b*NCH + c)*DS)*DI + d;
    #pragma unroll
    for (int n=0;n<DS;n++){ hend[base + (size_t)n*DI] = h[n]; Pout[base + (size_t)n*DI] = P[n]; }
}

__global__ void scan_pass2(const float* __restrict__ hend,
                           const float* __restrict__ P,
                           float* __restrict__ hin)
{
    int idx = blockIdx.x*blockDim.x + threadIdx.x;
    if (idx >= BSZ*DS*DI) return;
    int d = idx % DI;
    int n = (idx / DI) % DS;
    int b =  idx / (DI*DS);
    float h = 0.f;
    for (int c=0;c<NCH;c++){
        size_t off = (((size_t)b*NCH + c)*DS + n)*DI + d;
        hin[off] = h;
        h = fmaf(P[off], h, hend[off]);
    }
}

__global__ void scan_pass3(const float* __restrict__ dt,
                           const float* __restrict__ xc,
                           const float* __restrict__ dbc,
                           const float* __restrict__ A_log,
                           const float* __restrict__ Dp,
                           const float* __restrict__ xz,
                           const float* __restrict__ hin,
                           __nv_bfloat16* __restrict__ ygh,
                           __nv_bfloat16* __restrict__ ygl,
                           int dir)
{
    const int d = blockIdx.x*blockDim.x + threadIdx.x;
    const int c = blockIdx.y, b = blockIdx.z;
    __shared__ float sB[CS][DS];
    __shared__ float sC[CS][DS];
    for (int i = threadIdx.x; i < CS*2*DS; i += blockDim.x) {
        int sl = i / (2*DS), q = i % (2*DS);
        int p  = dir ? (SEQ-1 - (c*CS+sl)) : (c*CS+sl);
        float v = dbc[((size_t)b*SEQ + p)*64 + DR + q];
        if (q < DS) sB[sl][q] = v; else sC[sl][q-DS] = v;
    }
    __syncthreads();

    float A[DS];
    #pragma unroll
    for (int n=0;n<DS;n++) A[n] = -__expf(A_log[d*DS + n]);
    float h[DS];
    {
        size_t base = (((size_t)b*NCH + c)*DS)*DI + d;
        #pragma unroll
        for (int n=0;n<DS;n++) h[n] = hin[base + (size_t)n*DI];
    }
    const float Dval = Dp[d];

    for (int s=0;s<CS;s++){
        int p = dir ? (SEQ-1 - (c*CS+s)) : (c*CS+s);
        size_t off = ((size_t)b*SEQ + p)*DI + d;
        float dtv = dt[off];
        float xv  = xc[off];
        float dtx = dtv*xv;
        float y = 0.f;
        #pragma unroll
        for (int n=0;n<DS;n++){
            float dA = __expf(dtv*A[n]);
            h[n] = fmaf(dA, h[n], dtx*sB[s][n]);
            y = fmaf(h[n], sC[s][n], y);
        }
        float zz = xz[((size_t)b*SEQ + p)*(2*DI) + DI + d];
        float v = (y + xv*Dval) * (zz * sigmoidf_(zz));
        uint16_t hh,ll; split1(v,hh,ll);
        reinterpret_cast<uint16_t*>(ygh)[off] = hh;
        reinterpret_cast<uint16_t*>(ygl)[off] = ll;
    }
}

// ---------------- h = 0.5*(LN(x+mf; f) + LN(x+mb; b));  writes f32 + hi/lo ----------------
__global__ void ln_combine_kernel(const float* __restrict__ x,
                                  const float* __restrict__ mf,
                                  const float* __restrict__ mb,
                                  const float* __restrict__ gf, const float* __restrict__ bf,
                                  const float* __restrict__ gb, const float* __restrict__ bb,
                                  float* __restrict__ hout,
                                  __nv_bfloat16* __restrict__ hhi,
                                  __nv_bfloat16* __restrict__ hlo)
{
    const int row = blockIdx.x;
    const size_t base = (size_t)row*DMODEL;
    const int t4 = threadIdx.x;
    float4 x4  = *reinterpret_cast<const float4*>(&x [base + t4*4]);
    float4 f4  = *reinterpret_cast<const float4*>(&mf[base + t4*4]);
    float4 b4  = *reinterpret_cast<const float4*>(&mb[base + t4*4]);
    float a[4] = {x4.x+f4.x, x4.y+f4.y, x4.z+f4.z, x4.w+f4.w};
    float c[4] = {x4.x+b4.x, x4.y+b4.y, x4.z+b4.z, x4.w+b4.w};
    float sa=0, sa2=0, sc=0, sc2=0;
    #pragma unroll
    for (int i=0;i<4;i++){ sa+=a[i]; sa2+=a[i]*a[i]; sc+=c[i]; sc2+=c[i]*c[i]; }

    __shared__ float red[4][4];
    float vals[4] = {sa, sa2, sc, sc2};
    int warp = threadIdx.x>>5, lane = threadIdx.x&31;
    #pragma unroll
    for (int q=0;q<4;q++){
        float w = warpSum(vals[q]);
        if (lane==0) red[q][warp] = w;
    }
    __syncthreads();
    float tot[4];
    #pragma unroll
    for (int q=0;q<4;q++) tot[q] = red[q][0]+red[q][1]+red[q][2]+red[q][3];

    float ma = tot[0]*(1.f/DMODEL);
    float va = tot[1]*(1.f/DMODEL) - ma*ma;
    float ra = rsqrtf(va + LN_EPS);
    float mc = tot[2]*(1.f/DMODEL);
    float vc = tot[3]*(1.f/DMODEL) - mc*mc;
    float rc = rsqrtf(vc + LN_EPS);

    float4 out;
    float* po = &out.x;
    uint16_t hp[4], lp[4];
    #pragma unroll
    for (int i=0;i<4;i++){
        int col = t4*4+i;
        float la = (a[i]-ma)*ra*gf[col] + bf[col];
        float lc = (c[i]-mc)*rc*gb[col] + bb[col];
        float v = 0.5f*(la + lc);
        po[i] = v;
        split1(v, hp[i], lp[i]);
    }
    *reinterpret_cast<float4*>(&hout[base + t4*4]) = out;
    *reinterpret_cast<uint2*>(&hhi[base + t4*4]) =
        make_uint2((uint32_t)hp[0] | ((uint32_t)hp[1]<<16), (uint32_t)hp[2] | ((uint32_t)hp[3]<<16));
    *reinterpret_cast<uint2*>(&hlo[base + t4*4]) =
        make_uint2((uint32_t)lp[0] | ((uint32_t)lp[1]<<16), (uint32_t)lp[2] | ((uint32_t)lp[3]<<16));
}

// ---------------- out = LN(h + ff2; ln_ff) ----------------
__global__ void ln_final_kernel(const float* __restrict__ h,
                                const float* __restrict__ ff2,
                                const float* __restrict__ g, const float* __restrict__ bta,
                                float* __restrict__ out)
{
    const int row = blockIdx.x;
    const size_t base = (size_t)row*DMODEL;
    const int t4 = threadIdx.x;
    float4 h4 = *reinterpret_cast<const float4*>(&h  [base + t4*4]);
    float4 f4 = *reinterpret_cast<const float4*>(&ff2[base + t4*4]);
    float a[4] = {h4.x+f4.x, h4.y+f4.y, h4.z+f4.z, h4.w+f4.w};
    float sa=0, sa2=0;
    #pragma unroll
    for (int i=0;i<4;i++){ sa+=a[i]; sa2+=a[i]*a[i]; }

    __shared__ float red[2][4];
    int warp = threadIdx.x>>5, lane = threadIdx.x&31;
    float w0 = warpSum(sa), w1 = warpSum(sa2);
    if (lane==0){ red[0][warp]=w0; red[1][warp]=w1; }
    __syncthreads();
    float ts  = red[0][0]+red[0][1]+red[0][2]+red[0][3];
    float ts2 = red[1][0]+red[1][1]+red[1][2]+red[1][3];
    float mu = ts*(1.f/DMODEL);
    float var = ts2*(1.f/DMODEL) - mu*mu;
    float r = rsqrtf(var + LN_EPS);

    float4 o;
    float* po = &o.x;
    #pragma unroll
    for (int i=0;i<4;i++){
        int col = t4*4+i;
        po[i] = (a[i]-mu)*r*g[col] + bta[col];
    }
    *reinterpret_cast<float4*>(&out[base + t4*4]) = o;
}

// ---------------- host orchestration ----------------
extern "C" void kernel_launch(void* const* d_in, const int* in_sizes, int n_in,
                              void* d_out, int out_size)
{
    const float* x = (const float*)d_in[0];
    const float* in_w  [2] = {(const float*)d_in[1],  (const float*)d_in[10]};
    const float* conv_w[2] = {(const float*)d_in[2],  (const float*)d_in[11]};
    const float* conv_b[2] = {(const float*)d_in[3],  (const float*)d_in[12]};
    const float* xproj [2] = {(const float*)d_in[4],  (const float*)d_in[13]};
    const float* dt_w  [2] = {(const float*)d_in[5],  (const float*)d_in[14]};
    const float* dt_b  [2] = {(const float*)d_in[6],  (const float*)d_in[15]};
    const float* A_log [2] = {(const float*)d_in[7],  (const float*)d_in[16]};
    const float* Dp    [2] = {(const float*)d_in[8],  (const float*)d_in[17]};
    const float* out_w [2] = {(const float*)d_in[9],  (const float*)d_in[18]};
    const float* ln_f_g = (const float*)d_in[19];
    const float* ln_f_b = (const float*)d_in[20];
    const float* ln_b_g = (const float*)d_in[21];
    const float* ln_b_b = (const float*)d_in[22];
    const float* ln_ff_g= (const float*)d_in[23];
    const float* ln_ff_b= (const float*)d_in[24];
    const float* ffn_w1 = (const float*)d_in[25];
    const float* ffn_b1 = (const float*)d_in[26];
    const float* ffn_w2 = (const float*)d_in[27];
    const float* ffn_b2 = (const float*)d_in[28];
    float* outp = (float*)d_out;

    float *p_xz, *p_xc, *p_dbc, *p_dt, *p_mf, *p_mb, *p_h, *p_ff2;
    float *p_hend, *p_P, *p_hin;
    __nv_bfloat16 *p_xh, *p_xl, *p_xch, *p_xcl, *p_dbh, *p_dbl, *p_ygh, *p_ygl;
    __nv_bfloat16 *p_hh, *p_hl, *p_f1h, *p_f1l, *p_wh, *p_wl, *p_dwh, *p_dwl;
    cudaGetSymbolAddress((void**)&p_xz,  g_xz);
    cudaGetSymbolAddress((void**)&p_xc,  g_xc);
    cudaGetSymbolAddress((void**)&p_dbc, g_dbc);
    cudaGetSymbolAddress((void**)&p_dt,  g_dt);
    cudaGetSymbolAddress((void**)&p_mf,  g_mf);
    cudaGetSymbolAddress((void**)&p_mb,  g_mb);
    cudaGetSymbolAddress((void**)&p_h,   g_h);
    cudaGetSymbolAddress((void**)&p_ff2, g_ff2);
    cudaGetSymbolAddress((void**)&p_hend,g_hend);
    cudaGetSymbolAddress((void**)&p_P,   g_P);
    cudaGetSymbolAddress((void**)&p_hin, g_hin);
    cudaGetSymbolAddress((void**)&p_xh,  g_xh);   cudaGetSymbolAddress((void**)&p_xl,  g_xl);
    cudaGetSymbolAddress((void**)&p_xch, g_xch);  cudaGetSymbolAddress((void**)&p_xcl, g_xcl);
    cudaGetSymbolAddress((void**)&p_dbh, g_dbh);  cudaGetSymbolAddress((void**)&p_dbl, g_dbl);
    cudaGetSymbolAddress((void**)&p_ygh, g_ygh);  cudaGetSymbolAddress((void**)&p_ygl, g_ygl);
    cudaGetSymbolAddress((void**)&p_hh,  g_hh);   cudaGetSymbolAddress((void**)&p_hl,  g_hl);
    cudaGetSymbolAddress((void**)&p_f1h, g_f1h);  cudaGetSymbolAddress((void**)&p_f1l, g_f1l);
    cudaGetSymbolAddress((void**)&p_wh,  g_wh);   cudaGetSymbolAddress((void**)&p_wl,  g_wl);
    cudaGetSymbolAddress((void**)&p_dwh, g_dwh);  cudaGetSymbolAddress((void**)&p_dwl, g_dwl);

    const int SM128 = 2*(32768 + 2*128*128);  // 131072
    const int SM64  = 2*(32768 + 2*64*128);   // 98304
    cudaFuncSetAttribute(gemm_rs<128,0,1>, cudaFuncAttributeMaxDynamicSharedMemorySize, SM128);
    cudaFuncSetAttribute(gemm_rs<128,1,2>, cudaFuncAttributeMaxDynamicSharedMemorySize, SM128);
    cudaFuncSetAttribute(gemm_rs<128,2,1>, cudaFuncAttributeMaxDynamicSharedMemorySize, SM128);
    cudaFuncSetAttribute(gemm_rs<64,0,3>,  cudaFuncAttributeMaxDynamicSharedMemorySize, SM64);

    const int M = NTOK;

    // split x once
    split_f32<<<(NTOK*DMODEL/4 + 255)/256, 256>>>((const float4*)x, p_xh, p_xl, NTOK*DMODEL/4);

    for (int dir = 0; dir < 2; dir++) {
        // xz = x @ in_w^T   [M, 2048] K=512
        split_f32<<<(2*DI*DMODEL/4 + 255)/256, 256>>>((const float4*)in_w[dir], p_wh, p_wl, 2*DI*DMODEL/4);
        gemm_rs<128,0,1><<<dim3(2*DI/128, M/128), 256, SM128>>>(
            p_xh, p_xl, DMODEL, p_wh, p_wl, nullptr, p_xz, nullptr, nullptr, 2*DI, M, 2*DI, DMODEL);
        // conv + silu (writes xc f32 + hi/lo)
        conv_silu_kernel<<<(NTOK*DI/4)/256, 256>>>(p_xz, conv_w[dir], conv_b[dir], p_xc, p_xch, p_xcl, dir);
        // dbc = xc @ xproj^T  [M, 64] K=1024 (f32 for scan + hi/lo for dt GEMM)
        split_f32<<<(64*DI/4 + 255)/256, 256>>>((const float4*)xproj[dir], p_wh, p_wl, 64*DI/4);
        gemm_rs<64,0,3><<<dim3(1, M/128), 256, SM64>>>(
            p_xch, p_xcl, DI, p_wh, p_wl, nullptr, p_dbc, p_dbh, p_dbl, 64, M, 64, DI);
        // dt = softplus(dbc @ [dt_w|0]^T + dt_b)  [M, 1024] K=64
        pad_split_dtw<<<(DI*64)/256, 256>>>(dt_w[dir], p_dwh, p_dwl);
        gemm_rs<128,2,1><<<dim3(DI/128, M/128), 256, SM128>>>(
            p_dbh, p_dbl, 64, p_dwh, p_dwl, dt_b[dir], p_dt, nullptr, nullptr, DI, M, DI, 64);
        // chunked scan (pass3 writes yg hi/lo)
        {
            dim3 grid1(DI/256, NCH, BSZ);
            scan_pass1<<<grid1,256>>>(p_dt, p_xc, p_dbc, A_log[dir], p_hend, p_P, dir);
            scan_pass2<<<(BSZ*DS*DI)/256,256>>>(p_hend, p_P, p_hin);
            scan_pass3<<<grid1,256>>>(p_dt, p_xc, p_dbc, A_log[dir], Dp[dir], p_xz, p_hin, p_ygh, p_ygl, dir);
        }
        // mamba out = yg @ out_w^T  [M, 512] K=1024
        split_f32<<<(DMODEL*DI/4 + 255)/256, 256>>>((const float4*)out_w[dir], p_wh, p_wl, DMODEL*DI/4);
        gemm_rs<128,0,1><<<dim3(DMODEL/128, M/128), 256, SM128>>>(
            p_ygh, p_ygl, DI, p_wh, p_wl, nullptr, dir ? p_mb : p_mf, nullptr, nullptr, DMODEL, M, DMODEL, DI);
    }

    // h = 0.5*(LN(x+mf) + LN(x+mb))  (f32 + hi/lo)
    ln_combine_kernel<<<NTOK,128>>>(x, p_mf, p_mb, ln_f_g, ln_f_b, ln_b_g, ln_b_b, p_h, p_hh, p_hl);

    // ff1 = gelu(h @ w1^T + b1)  [M, 2048] K=512  (hi/lo only)
    split_f32<<<(DFF*DMODEL/4 + 255)/256, 256>>>((const float4*)ffn_w1, p_wh, p_wl, DFF*DMODEL/4);
    gemm_rs<128,1,2><<<dim3(DFF/128, M/128), 256, SM128>>>(
        p_hh, p_hl, DMODEL, p_wh, p_wl, ffn_b1, nullptr, p_f1h, p_f1l, DFF, M, DFF, DMODEL);
    // ff2 = ff1 @ w2^T + b2  [M, 512] K=2048
    split_f32<<<(DMODEL*DFF/4 + 255)/256, 256>>>((const float4*)ffn_w2, p_wh, p_wl, DMODEL*DFF/4);
    gemm_rs<128,0,1><<<dim3(DMODEL/128, M/128), 256, SM128>>>(
        p_f1h, p_f1l, DFF, p_wh, p_wl, ffn_b2, p_ff2, nullptr, nullptr, DMODEL, M, DMODEL, DFF);
    // out = LN(h + ff2)
    ln_final_kernel<<<NTOK,128>>>(p_h, p_ff2, ln_ff_g, ln_ff_b, outp);
}